// round 11
// baseline (speedup 1.0000x reference)
#include <cuda_runtime.h>
#include <cuda_bf16.h>
#include <math.h>
#include <stdint.h>

// Problem constants
#define B_ 2
#define S_ 2048
#define HID_ 2048
#define NH_ 8
#define HD_ 256
#define M_ 4096           // B*S
#define QKDIM_ (NH_*HD_)  // 2048
#define NQKV_ 2560        // 2048 (Q) + 256 (K) + 256 (V)

typedef __nv_bfloat16 bf16;

// ---------------------------------------------------------------------------
// Scratch (device globals: allocation-free per harness rules)
// ---------------------------------------------------------------------------
__device__ float g_qkv[M_ * NQKV_];                         // fused QKV output (fp32)

__device__ bf16 g_hsh[M_ * HID_],  g_hsl[M_ * HID_];        // split hidden_states
__device__ bf16 g_qh [M_ * QKDIM_], g_ql [M_ * QKDIM_];     // split Q (post-RoPE)
__device__ bf16 g_kh [M_ * HD_],   g_kl [M_ * HD_];         // split K
__device__ bf16 g_vth[B_ * HD_ * S_], g_vtl[B_ * HD_ * S_]; // V transposed [b][d][s]
__device__ bf16 g_ath[M_ * QKDIM_], g_atl[M_ * QKDIM_];     // split attention output

__device__ bf16 g_wallh[NQKV_ * HID_];                      // fused [Wq;Wk;Wv]^T hi
__device__ bf16 g_walll[NQKV_ * HID_];                      // fused lo
__device__ bf16 g_woh[QKDIM_ * HID_], g_wol[QKDIM_ * HID_];

// ---------------------------------------------------------------------------
// Helpers
// ---------------------------------------------------------------------------
__device__ __forceinline__ void split1(float x, bf16& h, bf16& l) {
    h = __float2bfloat16(x);
    l = __float2bfloat16(x - __bfloat162float(h));
}

__device__ __forceinline__ void mma16816(float (&d)[4], const uint32_t (&a)[4],
                                         uint32_t b0, uint32_t b1) {
    asm volatile(
        "mma.sync.aligned.m16n8k16.row.col.f32.bf16.bf16.f32 "
        "{%0,%1,%2,%3}, {%4,%5,%6,%7}, {%8,%9}, {%0,%1,%2,%3};\n"
        : "+f"(d[0]), "+f"(d[1]), "+f"(d[2]), "+f"(d[3])
        : "r"(a[0]), "r"(a[1]), "r"(a[2]), "r"(a[3]), "r"(b0), "r"(b1));
}

__device__ __forceinline__ void ldsm_x4(uint32_t (&r)[4], const bf16* p) {
    uint32_t a = (uint32_t)__cvta_generic_to_shared(p);
    asm volatile("ldmatrix.sync.aligned.m8n8.x4.shared.b16 {%0,%1,%2,%3}, [%4];\n"
        : "=r"(r[0]), "=r"(r[1]), "=r"(r[2]), "=r"(r[3]) : "r"(a));
}

__device__ __forceinline__ void cpasync16(bf16* s, const bf16* g) {
    uint32_t sa = (uint32_t)__cvta_generic_to_shared(s);
    asm volatile("cp.async.cg.shared.global [%0], [%1], 16;\n" :: "r"(sa), "l"(g));
}
__device__ __forceinline__ void cpcommit() {
    asm volatile("cp.async.commit_group;\n");
}
template<int N> __device__ __forceinline__ void cpwait() {
    asm volatile("cp.async.wait_group %0;\n" :: "n"(N));
}

// ---------------------------------------------------------------------------
// Elementwise split with strided source.
// ---------------------------------------------------------------------------
__global__ void split_strided_kernel(const float* __restrict__ in,
                                     bf16* __restrict__ oh, bf16* __restrict__ ol,
                                     int n, int colshift, int ldin) {
    int i = (blockIdx.x * blockDim.x + threadIdx.x) * 4;
    if (i >= n) return;
    int r = i >> colshift;
    int c = i & ((1 << colshift) - 1);
    float4 v = *(const float4*)(in + (size_t)r * ldin + c);
    bf16 h0,l0,h1,l1,h2,l2,h3,l3;
    split1(v.x,h0,l0); split1(v.y,h1,l1); split1(v.z,h2,l2); split1(v.w,h3,l3);
    __nv_bfloat162 a, b;
    a.x=h0; a.y=h1; b.x=h2; b.y=h3;
    *(__nv_bfloat162*)(oh+i)   = a; *(__nv_bfloat162*)(oh+i+2) = b;
    a.x=l0; a.y=l1; b.x=l2; b.y=l3;
    *(__nv_bfloat162*)(ol+i)   = a; *(__nv_bfloat162*)(ol+i+2) = b;
}

// ---------------------------------------------------------------------------
// Tiled transpose + split (generic).
// ---------------------------------------------------------------------------
__global__ void transpose_split_kernel(const float* __restrict__ in,
                                       bf16* __restrict__ oh, bf16* __restrict__ ol,
                                       int ldin, size_t bsIn, int ldout, size_t bsOut) {
    __shared__ float t[32][33];
    const float* ip = in + (size_t)blockIdx.z * bsIn;
    bf16* ohp = oh + (size_t)blockIdx.z * bsOut;
    bf16* olp = ol + (size_t)blockIdx.z * bsOut;
    const int r0 = blockIdx.y * 32, c0 = blockIdx.x * 32;
    #pragma unroll
    for (int i = 0; i < 4; i++) {
        int r = threadIdx.y + i * 8;
        t[r][threadIdx.x] = ip[(size_t)(r0 + r) * ldin + c0 + threadIdx.x];
    }
    __syncthreads();
    #pragma unroll
    for (int i = 0; i < 4; i++) {
        int c = threadIdx.y + i * 8;
        float v = t[threadIdx.x][c];
        bf16 h, l; split1(v, h, l);
        size_t o = (size_t)(c0 + c) * ldout + r0 + threadIdx.x;
        ohp[o] = h; olp[o] = l;
    }
}

// ---------------------------------------------------------------------------
// Fused QKV weight transpose+split: out [2560][2048] = [Wq^T; Wk^T; Wv^T].
// Column-range (32-aligned boundaries) selects the source weight.
// ---------------------------------------------------------------------------
__global__ void wqkv_transpose_kernel(const float* __restrict__ Wq,
                                      const float* __restrict__ Wk,
                                      const float* __restrict__ Wv,
                                      bf16* __restrict__ oh, bf16* __restrict__ ol) {
    __shared__ float t[32][33];
    const int c0 = blockIdx.x * 32;   // output row block (N dim, 0..2559)
    const int r0 = blockIdx.y * 32;   // HID block
    const float* src; int ldin, cbase;
    if (c0 < QKDIM_)            { src = Wq; ldin = QKDIM_; cbase = c0; }
    else if (c0 < QKDIM_ + HD_) { src = Wk; ldin = HD_;    cbase = c0 - QKDIM_; }
    else                        { src = Wv; ldin = HD_;    cbase = c0 - QKDIM_ - HD_; }
    #pragma unroll
    for (int i = 0; i < 4; i++) {
        int r = threadIdx.y + i * 8;
        t[r][threadIdx.x] = src[(size_t)(r0 + r) * ldin + cbase + threadIdx.x];
    }
    __syncthreads();
    #pragma unroll
    for (int i = 0; i < 4; i++) {
        int c = threadIdx.y + i * 8;
        float v = t[threadIdx.x][c];
        bf16 h, l; split1(v, h, l);
        size_t o = (size_t)(c0 + c) * HID_ + r0 + threadIdx.x;
        oh[o] = h; ol[o] = l;
    }
}

// ---------------------------------------------------------------------------
// GEMM: C[M,N] = A[M,K] @ B^T, A split bf16 [M][K], B split bf16 [N][K].
// 128x128 tile, BK=32, 256 threads (8 warps 4x2, warp tile 32x64).
// 2-stage cp.async + ldmatrix + 3-MMA bf16 split. 2 CTAs/SM.
// B fragments loaded per-p (8 live regs) to stay under the 128-reg cap.
// ---------------------------------------------------------------------------
#define GLDA 40                    // 32 + 8 halves pad (80B row: LDSM conflict-free)
#define PLANEH (128 * GLDA)        // 5120 halves per plane
#define STAGEH (4 * PLANEH)        // Ah, Al, Bh, Bl
#define GEMM_SMEM (2 * STAGEH * 2) // 2 stages: 81920 bytes

__global__ __launch_bounds__(256, 2) void gemm_bf16s(
    const bf16* __restrict__ Ah, const bf16* __restrict__ Al,
    const bf16* __restrict__ Bh, const bf16* __restrict__ Bl,
    float* __restrict__ C, int M, int N, int K)
{
    extern __shared__ bf16 sm[];
    const int tid = threadIdx.x;
    const int wid = tid >> 5, lane = tid & 31;
    const int g = lane >> 2, tg = lane & 3;
    const int m8 = lane >> 3, ri = lane & 7;     // ldmatrix lane decomposition
    const int wm = (wid & 3) * 32;
    const int wn = (wid >> 2) * 64;
    const int row0 = blockIdx.y * 128;
    const int col0 = blockIdx.x * 128;

    // cp.async mapping: thread -> row tid>>1, halves col (tid&1)*16
    const int lr = tid >> 1;
    const int lc = (tid & 1) * 16;
    const bf16* gA  = Ah + (size_t)(row0 + lr) * K + lc;
    const bf16* gAl = Al + (size_t)(row0 + lr) * K + lc;
    const bf16* gB  = Bh + (size_t)(col0 + lr) * K + lc;
    const bf16* gBl = Bl + (size_t)(col0 + lr) * K + lc;
    const int soff = lr * GLDA + lc;

    float acc[2][8][4] = {};
    const int nk = K / 32;

    auto load_stage = [&](int chunk, int st) {
        const int k0 = chunk * 32;
        bf16* s = sm + st * STAGEH + soff;
        cpasync16(s,            gA  + k0);  cpasync16(s + 8,            gA  + k0 + 8);
        cpasync16(s + PLANEH,   gAl + k0);  cpasync16(s + PLANEH + 8,   gAl + k0 + 8);
        cpasync16(s + 2*PLANEH, gB  + k0);  cpasync16(s + 2*PLANEH + 8, gB  + k0 + 8);
        cpasync16(s + 3*PLANEH, gBl + k0);  cpasync16(s + 3*PLANEH + 8, gBl + k0 + 8);
        cpcommit();
    };

    load_stage(0, 0);

    for (int i = 0; i < nk; i++) {
        if (i + 1 < nk) {
            load_stage(i + 1, (i + 1) & 1);
            cpwait<1>();
        } else {
            cpwait<0>();
        }
        __syncthreads();

        const bf16* pAh = sm + (i & 1) * STAGEH;
        const bf16* pAl = pAh + PLANEH;
        const bf16* pBh = pAh + 2 * PLANEH;
        const bf16* pBl = pAh + 3 * PLANEH;

        #pragma unroll
        for (int kk = 0; kk < 32; kk += 16) {
            uint32_t ah[2][4], al[2][4];
            #pragma unroll
            for (int mt = 0; mt < 2; mt++) {
                const int ao = (wm + mt * 16 + (m8 & 1) * 8 + ri) * GLDA + kk + (m8 >> 1) * 8;
                ldsm_x4(ah[mt], pAh + ao);
                ldsm_x4(al[mt], pAl + ao);
            }
            #pragma unroll
            for (int p = 0; p < 4; p++) {
                uint32_t bh[4], bl[4];   // only one p-pair live at a time
                const int bo = (wn + p * 16 + (m8 >> 1) * 8 + ri) * GLDA + kk + (m8 & 1) * 8;
                ldsm_x4(bh, pBh + bo);
                ldsm_x4(bl, pBl + bo);
                #pragma unroll
                for (int sub = 0; sub < 2; sub++) {
                    const int nt = p * 2 + sub;
                    const uint32_t h0 = bh[sub*2], h1 = bh[sub*2+1];
                    const uint32_t l0 = bl[sub*2], l1 = bl[sub*2+1];
                    #pragma unroll
                    for (int mt = 0; mt < 2; mt++) {
                        mma16816(acc[mt][nt], ah[mt], h0, h1);
                        mma16816(acc[mt][nt], ah[mt], l0, l1);
                        mma16816(acc[mt][nt], al[mt], h0, h1);
                    }
                }
            }
        }
        __syncthreads();
    }

    #pragma unroll
    for (int mt = 0; mt < 2; mt++)
        #pragma unroll
        for (int nt = 0; nt < 8; nt++) {
            const int r  = row0 + wm + mt * 16 + g;
            const int cn = col0 + wn + nt * 8 + tg * 2;
            float2 v01; v01.x = acc[mt][nt][0]; v01.y = acc[mt][nt][1];
            float2 v23; v23.x = acc[mt][nt][2]; v23.y = acc[mt][nt][3];
            *(float2*)(C + (size_t)r * N + cn)       = v01;
            *(float2*)(C + (size_t)(r + 8) * N + cn) = v23;
        }
}

// ---------------------------------------------------------------------------
// Fused RoPE + split: reads fp32 pairs from qkv, rotates, writes split bf16
// directly into qh/ql (Q) and kh/kl (K). qkv itself is left untouched.
// ---------------------------------------------------------------------------
__global__ void rope_split_kernel(const float* __restrict__ qkv,
                                  const int* __restrict__ pos,
                                  bf16* __restrict__ qh, bf16* __restrict__ ql,
                                  bf16* __restrict__ kh, bf16* __restrict__ kl)
{
    const int QP = B_ * S_ * NH_ * (HD_ / 2);
    const int KP = B_ * S_ * (HD_ / 2);
    int idx = blockIdx.x * blockDim.x + threadIdx.x;
    if (idx >= QP + KP) return;
    const float L2B = 13.28771237954945f;  // log2(10000)

    int i, bs;
    const float* base;
    bf16 *oh, *ol;
    size_t oo;
    if (idx < QP) {
        i  = idx & 127;
        const int h = (idx >> 7) & 7;
        bs = idx >> 10;
        base = qkv + (size_t)bs * NQKV_ + h * HD_;
        oo = (size_t)bs * QKDIM_ + h * HD_;
        oh = qh; ol = ql;
    } else {
        const int j = idx - QP;
        i  = j & 127;
        bs = j >> 7;
        base = qkv + (size_t)bs * NQKV_ + QKDIM_;
        oo = (size_t)bs * HD_;
        oh = kh; ol = kl;
    }
    const float inv = exp2f(-(float)(2 * i) * (L2B / 256.f));
    const float ang = (float)pos[bs] * inv;
    float sn, cs; sincosf(ang, &sn, &cs);
    const float x1 = base[i], x2 = base[i + 128];
    const float o1 = x1 * cs - x2 * sn;
    const float o2 = x2 * cs + x1 * sn;
    bf16 h1, l1, h2, l2;
    split1(o1, h1, l1); split1(o2, h2, l2);
    oh[oo + i]       = h1;  ol[oo + i]       = l1;
    oh[oo + i + 128] = h2;  ol[oo + i + 128] = l2;
}

// ---------------------------------------------------------------------------
// Flash attention, bf16-split MMAs + ldmatrix.
// Pipelined loads: separate K and V SMEM buffers — V(kt) issued before S-MMA
// (hidden under it), K(kt+1) issued after S-MMA reads K (hidden under
// softmax + PV). In-register softmax (shfl + pair-warp exchange).
// ---------------------------------------------------------------------------
#define AQ_LD 264
#define AP_LD 72
#define AQ_HALVES (64 * AQ_LD)    // 16896 (per plane, Q and K tiles)
#define AV_HALVES (256 * AP_LD)   // 18432 (per plane, V tile)
#define APB_HALVES (64 * AP_LD)   // 4608  (per plane, P tile)

#define ATT_SMEM_BYTES ((4*AQ_HALVES + 2*AV_HALVES + 2*APB_HALVES) * 2 + (3*64 + 256) * 4)

__global__ __launch_bounds__(256, 1) void attn_mma_kernel(
    const bf16* __restrict__ qh, const bf16* __restrict__ ql,
    const bf16* __restrict__ kh, const bf16* __restrict__ kl,
    const bf16* __restrict__ vth, const bf16* __restrict__ vtl,
    bf16* __restrict__ ath, bf16* __restrict__ atl)
{
    extern __shared__ char smraw[];
    bf16* Qh = (bf16*)smraw;
    bf16* Ql = Qh + AQ_HALVES;
    bf16* Kh = Ql + AQ_HALVES;
    bf16* Kl = Kh + AQ_HALVES;
    bf16* Vh = Kl + AQ_HALVES;
    bf16* Vl = Vh + AV_HALVES;
    bf16* Ph = Vl + AV_HALVES;
    bf16* Pl = Ph + APB_HALVES;
    float* Ms = (float*)(Pl + APB_HALVES);
    float* Ls = Ms + 64;
    float* Cr = Ls + 64;
    float* Mx = Cr + 64;    // [128] pair-warp max exchange
    float* Sx = Mx + 128;   // [128] pair-warp sum exchange

    const int qt = (int)gridDim.x - 1 - (int)blockIdx.x;  // heavy tiles first
    const int h  = blockIdx.y;
    const int b  = blockIdx.z;
    const int tid = threadIdx.x;
    const int wid = tid >> 5, lane = tid & 31;
    const int g = lane >> 2, tg = lane & 3;
    const int m8 = lane >> 3, ri = lane & 7;
    const int wm  = (wid & 3) * 16;
    const int wn2 = (wid >> 2) * 32;
    const int wd  = (wid >> 2) * 128;
    const int half = wid >> 2;
    const int barid = (wid & 3) + 1;
    const int q0 = qt * 64;
    const float scale = 0.0625f;

    // prologue: Q tile (group) then K(0) tile (group)
    {
        #pragma unroll
        for (int j = 0; j < 8; j++) {
            const int c = tid + 256 * j;
            const int r = c >> 5, cc = (c & 31) * 8;
            const size_t go = (size_t)(b * S_ + q0 + r) * QKDIM_ + h * HD_ + cc;
            cpasync16(Qh + r * AQ_LD + cc, qh + go);
            cpasync16(Ql + r * AQ_LD + cc, ql + go);
        }
        cpcommit();
        #pragma unroll
        for (int j = 0; j < 8; j++) {
            const int c = tid + 256 * j;
            const int r = c >> 5, cc = (c & 31) * 8;
            const size_t go = (size_t)(b * S_ + r) * HD_ + cc;
            cpasync16(Kh + r * AQ_LD + cc, kh + go);
            cpasync16(Kl + r * AQ_LD + cc, kl + go);
        }
        cpcommit();
    }
    if (tid < 64) { Ms[tid] = -INFINITY; Ls[tid] = 0.f; Cr[tid] = 0.f; }

    float oc[16][4] = {};

    for (int kt = 0; kt <= qt; ++kt) {
        const int k0 = kt * 64;
        cpwait<0>();       // K(kt) (and Q on first iter) landed
        __syncthreads();   // B: K visible; PV(kt-1) done with V and P buffers

        // Issue V(kt) load now — hidden under S-MMA.
        #pragma unroll
        for (int j = 0; j < 8; j++) {
            const int c = tid + 256 * j;
            const int r = c >> 3, cc = (c & 7) * 8;
            const size_t go = (size_t)b * HD_ * S_ + (size_t)r * S_ + k0 + cc;
            cpasync16(Vh + r * AP_LD + cc, vth + go);
            cpasync16(Vl + r * AP_LD + cc, vtl + go);
        }
        cpcommit();        // group V

        // S = Q @ K^T via 3-MMA split (ldmatrix fragments)
        float sc[4][4] = {};
        #pragma unroll
        for (int kk = 0; kk < 256; kk += 16) {
            uint32_t ah[4], al[4];
            {
                const int ao = (wm + (m8 & 1) * 8 + ri) * AQ_LD + kk + (m8 >> 1) * 8;
                ldsm_x4(ah, Qh + ao);
                ldsm_x4(al, Ql + ao);
            }
            uint32_t bh[2][4], bl[2][4];
            #pragma unroll
            for (int p = 0; p < 2; p++) {
                const int bo = (wn2 + p * 16 + (m8 >> 1) * 8 + ri) * AQ_LD + kk + (m8 & 1) * 8;
                ldsm_x4(bh[p], Kh + bo);
                ldsm_x4(bl[p], Kl + bo);
            }
            #pragma unroll
            for (int p = 0; p < 2; p++)
                #pragma unroll
                for (int sub = 0; sub < 2; sub++) {
                    const int nt = p * 2 + sub;
                    mma16816(sc[nt], ah, bh[p][sub*2], bh[p][sub*2+1]);
                    mma16816(sc[nt], ah, bl[p][sub*2], bl[p][sub*2+1]);
                    mma16816(sc[nt], al, bh[p][sub*2], bh[p][sub*2+1]);
                }
        }

        // scale + causal mask in registers
        const int r0g = q0 + wm + g;
        const int r1g = r0g + 8;
        #pragma unroll
        for (int nt = 0; nt < 4; nt++) {
            const int col = k0 + wn2 + nt * 8 + tg * 2;
            sc[nt][0] = (col     > r0g) ? -1e30f : sc[nt][0] * scale;
            sc[nt][1] = (col + 1 > r0g) ? -1e30f : sc[nt][1] * scale;
            sc[nt][2] = (col     > r1g) ? -1e30f : sc[nt][2] * scale;
            sc[nt][3] = (col + 1 > r1g) ? -1e30f : sc[nt][3] * scale;
        }

        __syncthreads();   // C: all warps done reading K(kt)

        // Issue K(kt+1) load — hidden under softmax + PV.
        if (kt < qt) {
            const int kn = k0 + 64;
            #pragma unroll
            for (int j = 0; j < 8; j++) {
                const int c = tid + 256 * j;
                const int r = c >> 5, cc = (c & 31) * 8;
                const size_t go = (size_t)(b * S_ + kn + r) * HD_ + cc;
                cpasync16(Kh + r * AQ_LD + cc, kh + go);
                cpasync16(Kl + r * AQ_LD + cc, kl + go);
            }
            cpcommit();    // group K(kt+1)
        }

        // In-register softmax. Rows r0=wm+g, r1=r0+8; 8 cols/row per thread.
        const int lr0 = wm + g, lr1 = lr0 + 8;
        float mx0 = -INFINITY, mx1 = -INFINITY;
        #pragma unroll
        for (int nt = 0; nt < 4; nt++) {
            mx0 = fmaxf(mx0, fmaxf(sc[nt][0], sc[nt][1]));
            mx1 = fmaxf(mx1, fmaxf(sc[nt][2], sc[nt][3]));
        }
        mx0 = fmaxf(mx0, __shfl_xor_sync(0xffffffffu, mx0, 1));
        mx0 = fmaxf(mx0, __shfl_xor_sync(0xffffffffu, mx0, 2));
        mx1 = fmaxf(mx1, __shfl_xor_sync(0xffffffffu, mx1, 1));
        mx1 = fmaxf(mx1, __shfl_xor_sync(0xffffffffu, mx1, 2));
        if (tg == 0) { Mx[half * 64 + lr0] = mx0; Mx[half * 64 + lr1] = mx1; }
        asm volatile("bar.sync %0, 64;" :: "r"(barid) : "memory");   // D (pair)

        const float mo0 = Ms[lr0], mo1 = Ms[lr1];
        const float mn0 = fmaxf(fmaxf(Mx[lr0], Mx[64 + lr0]), mo0);
        const float mn1 = fmaxf(fmaxf(Mx[lr1], Mx[64 + lr1]), mo1);
        float sum0 = 0.f, sum1 = 0.f;
        #pragma unroll
        for (int nt = 0; nt < 4; nt++) {
            const int colL = wn2 + nt * 8 + tg * 2;
            const float p0 = __expf(sc[nt][0] - mn0);
            const float p1 = __expf(sc[nt][1] - mn0);
            const float p2 = __expf(sc[nt][2] - mn1);
            const float p3 = __expf(sc[nt][3] - mn1);
            sum0 += p0 + p1; sum1 += p2 + p3;
            bf16 hb0,lb0,hb1,lb1,hb2,lb2,hb3,lb3;
            split1(p0,hb0,lb0); split1(p1,hb1,lb1);
            split1(p2,hb2,lb2); split1(p3,hb3,lb3);
            __nv_bfloat162 t;
            t.x=hb0; t.y=hb1; *(__nv_bfloat162*)(Ph + lr0 * AP_LD + colL) = t;
            t.x=lb0; t.y=lb1; *(__nv_bfloat162*)(Pl + lr0 * AP_LD + colL) = t;
            t.x=hb2; t.y=hb3; *(__nv_bfloat162*)(Ph + lr1 * AP_LD + colL) = t;
            t.x=lb2; t.y=lb3; *(__nv_bfloat162*)(Pl + lr1 * AP_LD + colL) = t;
        }
        sum0 += __shfl_xor_sync(0xffffffffu, sum0, 1);
        sum0 += __shfl_xor_sync(0xffffffffu, sum0, 2);
        sum1 += __shfl_xor_sync(0xffffffffu, sum1, 1);
        sum1 += __shfl_xor_sync(0xffffffffu, sum1, 2);
        if (tg == 0) { Sx[half * 64 + lr0] = sum0; Sx[half * 64 + lr1] = sum1; }
        asm volatile("bar.sync %0, 64;" :: "r"(barid) : "memory");   // E (pair)

        // one thread per row (warps 0-3, lanes 0-15) updates running state
        if (wid < 4 && lane < 16) {
            const int row = wm + lane;
            const float mo = Ms[row];
            const float mn = fmaxf(fmaxf(Mx[row], Mx[64 + row]), mo);
            const float corr = (mo == -INFINITY) ? 0.f : __expf(mo - mn);
            Ls[row] = Ls[row] * corr + Sx[row] + Sx[64 + row];
            Ms[row] = mn;
            Cr[row] = corr;
        }
        // V must be complete; K(kt+1) (the most recent group) may stay in flight.
        if (kt < qt) cpwait<1>(); else cpwait<0>();
        __syncthreads();   // F: V landed, Ph/Pl + Ls/Ms/Cr visible

        // Rescale accumulator, then O += P @ V (3-MMA split, ldmatrix)
        const float cr0 = Cr[wm + g], cr1 = Cr[wm + g + 8];
        #pragma unroll
        for (int nt = 0; nt < 16; nt++) {
            oc[nt][0] *= cr0; oc[nt][1] *= cr0;
            oc[nt][2] *= cr1; oc[nt][3] *= cr1;
        }
        #pragma unroll
        for (int kk = 0; kk < 64; kk += 16) {
            uint32_t pa[4], pl_[4];
            {
                const int ao = (wm + (m8 & 1) * 8 + ri) * AP_LD + kk + (m8 >> 1) * 8;
                ldsm_x4(pa,  Ph + ao);
                ldsm_x4(pl_, Pl + ao);
            }
            #pragma unroll
            for (int p = 0; p < 8; p++) {
                uint32_t bh[4], bl[4];
                const int bo = (wd + p * 16 + (m8 >> 1) * 8 + ri) * AP_LD + kk + (m8 & 1) * 8;
                ldsm_x4(bh, Vh + bo);
                ldsm_x4(bl, Vl + bo);
                #pragma unroll
                for (int sub = 0; sub < 2; sub++) {
                    const int nt = p * 2 + sub;
                    mma16816(oc[nt], pa,  bh[sub*2], bh[sub*2+1]);
                    mma16816(oc[nt], pa,  bl[sub*2], bl[sub*2+1]);
                    mma16816(oc[nt], pl_, bh[sub*2], bh[sub*2+1]);
                }
            }
        }
    }

    const float inv0 = 1.f / Ls[wm + g];
    const float inv1 = 1.f / Ls[wm + g + 8];
    #pragma unroll
    for (int nt = 0; nt < 16; nt++) {
        const int d = wd + nt * 8 + tg * 2;
        const size_t base0 = (size_t)(b * S_ + q0 + wm + g) * QKDIM_ + h * HD_ + d;
        const size_t base1 = base0 + 8 * QKDIM_;
        const float v0 = oc[nt][0] * inv0, v1 = oc[nt][1] * inv0;
        const float v2 = oc[nt][2] * inv1, v3 = oc[nt][3] * inv1;
        bf16 h0,l0,h1,l1,h2,l2,h3,l3;
        split1(v0,h0,l0); split1(v1,h1,l1); split1(v2,h2,l2); split1(v3,h3,l3);
        __nv_bfloat162 t;
        t.x=h0; t.y=h1; *(__nv_bfloat162*)(ath + base0) = t;
        t.x=l0; t.y=l1; *(__nv_bfloat162*)(atl + base0) = t;
        t.x=h2; t.y=h3; *(__nv_bfloat162*)(ath + base1) = t;
        t.x=l2; t.y=l3; *(__nv_bfloat162*)(atl + base1) = t;
    }
}

// ---------------------------------------------------------------------------
// Launch
// Inputs: 0=hidden_states 1=attention_mask(unused) 2=position_ids
//         3=Wq 4=Wk 5=Wv 6=Wo
// ---------------------------------------------------------------------------
extern "C" void kernel_launch(void* const* d_in, const int* in_sizes, int n_in,
                              void* d_out, int out_size) {
    (void)in_sizes; (void)n_in; (void)out_size;
    const float* hs  = (const float*)d_in[0];
    const int*   pos = (const int*)  d_in[2];
    const float* Wq  = (const float*)d_in[3];
    const float* Wk  = (const float*)d_in[4];
    const float* Wv  = (const float*)d_in[5];
    const float* Wo  = (const float*)d_in[6];
    float* out = (float*)d_out;

    float *qkv;
    bf16 *hsh,*hsl,*qh,*ql,*kh,*kl,*vth,*vtl,*ath,*atl;
    bf16 *wallh,*walll,*woh,*wol;
    cudaGetSymbolAddress((void**)&qkv, g_qkv);
    cudaGetSymbolAddress((void**)&hsh, g_hsh); cudaGetSymbolAddress((void**)&hsl, g_hsl);
    cudaGetSymbolAddress((void**)&qh,  g_qh);  cudaGetSymbolAddress((void**)&ql,  g_ql);
    cudaGetSymbolAddress((void**)&kh,  g_kh);  cudaGetSymbolAddress((void**)&kl,  g_kl);
    cudaGetSymbolAddress((void**)&vth, g_vth); cudaGetSymbolAddress((void**)&vtl, g_vtl);
    cudaGetSymbolAddress((void**)&ath, g_ath); cudaGetSymbolAddress((void**)&atl, g_atl);
    cudaGetSymbolAddress((void**)&wallh, g_wallh); cudaGetSymbolAddress((void**)&walll, g_walll);
    cudaGetSymbolAddress((void**)&woh, g_woh); cudaGetSymbolAddress((void**)&wol, g_wol);

    cudaFuncSetAttribute(gemm_bf16s,
        cudaFuncAttributeMaxDynamicSharedMemorySize, GEMM_SMEM);
    cudaFuncSetAttribute(attn_mma_kernel,
        cudaFuncAttributeMaxDynamicSharedMemorySize, ATT_SMEM_BYTES);

    const dim3 tb(32, 8);

    // Split hidden states; transpose+split weights (QKV fused into one launch)
    split_strided_kernel<<<(M_ * HID_ / 4 + 255) / 256, 256>>>(
        hs, hsh, hsl, M_ * HID_, 11, HID_);
    wqkv_transpose_kernel<<<dim3(NQKV_ / 32, HID_ / 32), tb>>>(
        Wq, Wk, Wv, wallh, walll);
    transpose_split_kernel<<<dim3(64, 64, 1), tb>>>(
        Wo, woh, wol, HID_, 0, QKDIM_, 0);

    // Fused QKV projection (tensor core): C[4096][2560]
    gemm_bf16s<<<dim3(NQKV_ / 128, M_ / 128), 256, GEMM_SMEM>>>(
        hsh, hsl, wallh, walll, qkv, M_, NQKV_, HID_);

    // Fused RoPE + split: qkv -> split Q/K directly
    {
        const int total = B_ * S_ * NH_ * (HD_ / 2) + B_ * S_ * (HD_ / 2);
        rope_split_kernel<<<(total + 255) / 256, 256>>>(qkv, pos, qh, ql, kh, kl);
    }

    // Transpose+split V per batch
    transpose_split_kernel<<<dim3(8, 64, B_), tb>>>(
        qkv + QKDIM_ + HD_, vth, vtl,
        NQKV_, (size_t)S_ * NQKV_, S_, (size_t)HD_ * S_);

    // Attention (tensor core flash)
    attn_mma_kernel<<<dim3(S_ / 64, NH_, B_), 256, ATT_SMEM_BYTES>>>(
        qh, ql, kh, kl, vth, vtl, ath, atl);

    // Output projection (tensor core)
    gemm_bf16s<<<dim3(HID_ / 128, M_ / 128), 256, GEMM_SMEM>>>(
        ath, atl, woh, wol, out, M_, HID_, HID_);
}

// round 12
// speedup vs baseline: 1.0047x; 1.0047x over previous
#include <cuda_runtime.h>
#include <cuda_bf16.h>
#include <math.h>
#include <stdint.h>

// Problem constants
#define B_ 2
#define S_ 2048
#define HID_ 2048
#define NH_ 8
#define HD_ 256
#define M_ 4096           // B*S
#define QKDIM_ (NH_*HD_)  // 2048
#define NQKV_ 2560        // 2048 (Q) + 256 (K) + 256 (V)

typedef __nv_bfloat16 bf16;

// ---------------------------------------------------------------------------
// Scratch (device globals: allocation-free per harness rules)
// ---------------------------------------------------------------------------
__device__ float g_qkv[M_ * NQKV_];                         // fused QKV output (fp32)

__device__ bf16 g_hsh[M_ * HID_],  g_hsl[M_ * HID_];        // split hidden_states
__device__ bf16 g_qh [M_ * QKDIM_], g_ql [M_ * QKDIM_];     // split Q (post-RoPE)
__device__ bf16 g_kh [M_ * HD_],   g_kl [M_ * HD_];         // split K
__device__ bf16 g_vth[B_ * HD_ * S_], g_vtl[B_ * HD_ * S_]; // V transposed [b][d][s]
__device__ bf16 g_ath[M_ * QKDIM_], g_atl[M_ * QKDIM_];     // split attention output

__device__ bf16 g_wallh[NQKV_ * HID_];                      // fused [Wq;Wk;Wv]^T hi
__device__ bf16 g_walll[NQKV_ * HID_];                      // fused lo
__device__ bf16 g_woh[QKDIM_ * HID_], g_wol[QKDIM_ * HID_];

// ---------------------------------------------------------------------------
// Helpers
// ---------------------------------------------------------------------------
__device__ __forceinline__ void split1(float x, bf16& h, bf16& l) {
    h = __float2bfloat16(x);
    l = __float2bfloat16(x - __bfloat162float(h));
}

__device__ __forceinline__ void mma16816(float (&d)[4], const uint32_t (&a)[4],
                                         uint32_t b0, uint32_t b1) {
    asm volatile(
        "mma.sync.aligned.m16n8k16.row.col.f32.bf16.bf16.f32 "
        "{%0,%1,%2,%3}, {%4,%5,%6,%7}, {%8,%9}, {%0,%1,%2,%3};\n"
        : "+f"(d[0]), "+f"(d[1]), "+f"(d[2]), "+f"(d[3])
        : "r"(a[0]), "r"(a[1]), "r"(a[2]), "r"(a[3]), "r"(b0), "r"(b1));
}

__device__ __forceinline__ void ldsm_x4(uint32_t (&r)[4], const bf16* p) {
    uint32_t a = (uint32_t)__cvta_generic_to_shared(p);
    asm volatile("ldmatrix.sync.aligned.m8n8.x4.shared.b16 {%0,%1,%2,%3}, [%4];\n"
        : "=r"(r[0]), "=r"(r[1]), "=r"(r[2]), "=r"(r[3]) : "r"(a));
}

__device__ __forceinline__ void cpasync16(bf16* s, const bf16* g) {
    uint32_t sa = (uint32_t)__cvta_generic_to_shared(s);
    asm volatile("cp.async.cg.shared.global [%0], [%1], 16;\n" :: "r"(sa), "l"(g));
}
__device__ __forceinline__ void cpcommit() {
    asm volatile("cp.async.commit_group;\n");
}
template<int N> __device__ __forceinline__ void cpwait() {
    asm volatile("cp.async.wait_group %0;\n" :: "n"(N));
}

// ---------------------------------------------------------------------------
// Elementwise split with strided source.
// ---------------------------------------------------------------------------
__global__ void split_strided_kernel(const float* __restrict__ in,
                                     bf16* __restrict__ oh, bf16* __restrict__ ol,
                                     int n, int colshift, int ldin) {
    int i = (blockIdx.x * blockDim.x + threadIdx.x) * 4;
    if (i >= n) return;
    int r = i >> colshift;
    int c = i & ((1 << colshift) - 1);
    float4 v = *(const float4*)(in + (size_t)r * ldin + c);
    bf16 h0,l0,h1,l1,h2,l2,h3,l3;
    split1(v.x,h0,l0); split1(v.y,h1,l1); split1(v.z,h2,l2); split1(v.w,h3,l3);
    __nv_bfloat162 a, b;
    a.x=h0; a.y=h1; b.x=h2; b.y=h3;
    *(__nv_bfloat162*)(oh+i)   = a; *(__nv_bfloat162*)(oh+i+2) = b;
    a.x=l0; a.y=l1; b.x=l2; b.y=l3;
    *(__nv_bfloat162*)(ol+i)   = a; *(__nv_bfloat162*)(ol+i+2) = b;
}

// ---------------------------------------------------------------------------
// Tiled transpose + split (generic).
// ---------------------------------------------------------------------------
__global__ void transpose_split_kernel(const float* __restrict__ in,
                                       bf16* __restrict__ oh, bf16* __restrict__ ol,
                                       int ldin, size_t bsIn, int ldout, size_t bsOut) {
    __shared__ float t[32][33];
    const float* ip = in + (size_t)blockIdx.z * bsIn;
    bf16* ohp = oh + (size_t)blockIdx.z * bsOut;
    bf16* olp = ol + (size_t)blockIdx.z * bsOut;
    const int r0 = blockIdx.y * 32, c0 = blockIdx.x * 32;
    #pragma unroll
    for (int i = 0; i < 4; i++) {
        int r = threadIdx.y + i * 8;
        t[r][threadIdx.x] = ip[(size_t)(r0 + r) * ldin + c0 + threadIdx.x];
    }
    __syncthreads();
    #pragma unroll
    for (int i = 0; i < 4; i++) {
        int c = threadIdx.y + i * 8;
        float v = t[threadIdx.x][c];
        bf16 h, l; split1(v, h, l);
        size_t o = (size_t)(c0 + c) * ldout + r0 + threadIdx.x;
        ohp[o] = h; olp[o] = l;
    }
}

// ---------------------------------------------------------------------------
// Fused QKV weight transpose+split: out [2560][2048] = [Wq^T; Wk^T; Wv^T].
// ---------------------------------------------------------------------------
__global__ void wqkv_transpose_kernel(const float* __restrict__ Wq,
                                      const float* __restrict__ Wk,
                                      const float* __restrict__ Wv,
                                      bf16* __restrict__ oh, bf16* __restrict__ ol) {
    __shared__ float t[32][33];
    const int c0 = blockIdx.x * 32;   // output row block (N dim, 0..2559)
    const int r0 = blockIdx.y * 32;   // HID block
    const float* src; int ldin, cbase;
    if (c0 < QKDIM_)            { src = Wq; ldin = QKDIM_; cbase = c0; }
    else if (c0 < QKDIM_ + HD_) { src = Wk; ldin = HD_;    cbase = c0 - QKDIM_; }
    else                        { src = Wv; ldin = HD_;    cbase = c0 - QKDIM_ - HD_; }
    #pragma unroll
    for (int i = 0; i < 4; i++) {
        int r = threadIdx.y + i * 8;
        t[r][threadIdx.x] = src[(size_t)(r0 + r) * ldin + cbase + threadIdx.x];
    }
    __syncthreads();
    #pragma unroll
    for (int i = 0; i < 4; i++) {
        int c = threadIdx.y + i * 8;
        float v = t[threadIdx.x][c];
        bf16 h, l; split1(v, h, l);
        size_t o = (size_t)(c0 + c) * HID_ + r0 + threadIdx.x;
        oh[o] = h; ol[o] = l;
    }
}

// ---------------------------------------------------------------------------
// GEMM: C[M,N] = A[M,K] @ B^T, A split bf16 [M][K], B split bf16 [N][K].
// 128x128 tile, BK=32, 256 threads (8 warps 4x2, warp tile 32x64).
// 2-stage cp.async + ldmatrix + 3-MMA bf16 split. 2 CTAs/SM.
// SINGLE __syncthreads per chunk: load(i+1) issued after the sync (safe:
// sync proves all warps finished compute(i-1), the only reader of that buf).
// ---------------------------------------------------------------------------
#define GLDA 40                    // 32 + 8 halves pad (80B row: LDSM conflict-free)
#define PLANEH (128 * GLDA)        // 5120 halves per plane
#define STAGEH (4 * PLANEH)        // Ah, Al, Bh, Bl
#define GEMM_SMEM (2 * STAGEH * 2) // 2 stages: 81920 bytes

__global__ __launch_bounds__(256, 2) void gemm_bf16s(
    const bf16* __restrict__ Ah, const bf16* __restrict__ Al,
    const bf16* __restrict__ Bh, const bf16* __restrict__ Bl,
    float* __restrict__ C, int M, int N, int K)
{
    extern __shared__ bf16 sm[];
    const int tid = threadIdx.x;
    const int wid = tid >> 5, lane = tid & 31;
    const int g = lane >> 2, tg = lane & 3;
    const int m8 = lane >> 3, ri = lane & 7;     // ldmatrix lane decomposition
    const int wm = (wid & 3) * 32;
    const int wn = (wid >> 2) * 64;
    const int row0 = blockIdx.y * 128;
    const int col0 = blockIdx.x * 128;

    // cp.async mapping: thread -> row tid>>1, halves col (tid&1)*16
    const int lr = tid >> 1;
    const int lc = (tid & 1) * 16;
    const bf16* gA  = Ah + (size_t)(row0 + lr) * K + lc;
    const bf16* gAl = Al + (size_t)(row0 + lr) * K + lc;
    const bf16* gB  = Bh + (size_t)(col0 + lr) * K + lc;
    const bf16* gBl = Bl + (size_t)(col0 + lr) * K + lc;
    const int soff = lr * GLDA + lc;

    float acc[2][8][4] = {};
    const int nk = K / 32;

    auto load_stage = [&](int chunk, int st) {
        const int k0 = chunk * 32;
        bf16* s = sm + st * STAGEH + soff;
        cpasync16(s,            gA  + k0);  cpasync16(s + 8,            gA  + k0 + 8);
        cpasync16(s + PLANEH,   gAl + k0);  cpasync16(s + PLANEH + 8,   gAl + k0 + 8);
        cpasync16(s + 2*PLANEH, gB  + k0);  cpasync16(s + 2*PLANEH + 8, gB  + k0 + 8);
        cpasync16(s + 3*PLANEH, gBl + k0);  cpasync16(s + 3*PLANEH + 8, gBl + k0 + 8);
        cpcommit();
    };

    load_stage(0, 0);

    for (int i = 0; i < nk; i++) {
        cpwait<0>();        // stage i landed (this thread's chunks)
        __syncthreads();    // all threads' stage-i data visible; compute(i-1) done
        if (i + 1 < nk) load_stage(i + 1, (i + 1) & 1);

        const bf16* pAh = sm + (i & 1) * STAGEH;
        const bf16* pAl = pAh + PLANEH;
        const bf16* pBh = pAh + 2 * PLANEH;
        const bf16* pBl = pAh + 3 * PLANEH;

        #pragma unroll
        for (int kk = 0; kk < 32; kk += 16) {
            uint32_t ah[2][4], al[2][4];
            #pragma unroll
            for (int mt = 0; mt < 2; mt++) {
                const int ao = (wm + mt * 16 + (m8 & 1) * 8 + ri) * GLDA + kk + (m8 >> 1) * 8;
                ldsm_x4(ah[mt], pAh + ao);
                ldsm_x4(al[mt], pAl + ao);
            }
            uint32_t bh[4][4], bl[4][4];
            #pragma unroll
            for (int p = 0; p < 4; p++) {
                const int bo = (wn + p * 16 + (m8 >> 1) * 8 + ri) * GLDA + kk + (m8 & 1) * 8;
                ldsm_x4(bh[p], pBh + bo);
                ldsm_x4(bl[p], pBl + bo);
            }
            #pragma unroll
            for (int p = 0; p < 4; p++)
                #pragma unroll
                for (int sub = 0; sub < 2; sub++) {
                    const int nt = p * 2 + sub;
                    const uint32_t h0 = bh[p][sub*2], h1 = bh[p][sub*2+1];
                    const uint32_t l0 = bl[p][sub*2], l1 = bl[p][sub*2+1];
                    #pragma unroll
                    for (int mt = 0; mt < 2; mt++) {
                        mma16816(acc[mt][nt], ah[mt], h0, h1);
                        mma16816(acc[mt][nt], ah[mt], l0, l1);
                        mma16816(acc[mt][nt], al[mt], h0, h1);
                    }
                }
        }
    }

    #pragma unroll
    for (int mt = 0; mt < 2; mt++)
        #pragma unroll
        for (int nt = 0; nt < 8; nt++) {
            const int r  = row0 + wm + mt * 16 + g;
            const int cn = col0 + wn + nt * 8 + tg * 2;
            float2 v01; v01.x = acc[mt][nt][0]; v01.y = acc[mt][nt][1];
            float2 v23; v23.x = acc[mt][nt][2]; v23.y = acc[mt][nt][3];
            *(float2*)(C + (size_t)r * N + cn)       = v01;
            *(float2*)(C + (size_t)(r + 8) * N + cn) = v23;
        }
}

// ---------------------------------------------------------------------------
// Fused RoPE + split: reads fp32 pairs from qkv, rotates, writes split bf16
// directly into qh/ql (Q) and kh/kl (K).
// ---------------------------------------------------------------------------
__global__ void rope_split_kernel(const float* __restrict__ qkv,
                                  const int* __restrict__ pos,
                                  bf16* __restrict__ qh, bf16* __restrict__ ql,
                                  bf16* __restrict__ kh, bf16* __restrict__ kl)
{
    const int QP = B_ * S_ * NH_ * (HD_ / 2);
    const int KP = B_ * S_ * (HD_ / 2);
    int idx = blockIdx.x * blockDim.x + threadIdx.x;
    if (idx >= QP + KP) return;
    const float L2B = 13.28771237954945f;  // log2(10000)

    int i, bs;
    const float* base;
    bf16 *oh, *ol;
    size_t oo;
    if (idx < QP) {
        i  = idx & 127;
        const int h = (idx >> 7) & 7;
        bs = idx >> 10;
        base = qkv + (size_t)bs * NQKV_ + h * HD_;
        oo = (size_t)bs * QKDIM_ + h * HD_;
        oh = qh; ol = ql;
    } else {
        const int j = idx - QP;
        i  = j & 127;
        bs = j >> 7;
        base = qkv + (size_t)bs * NQKV_ + QKDIM_;
        oo = (size_t)bs * HD_;
        oh = kh; ol = kl;
    }
    const float inv = exp2f(-(float)(2 * i) * (L2B / 256.f));
    const float ang = (float)pos[bs] * inv;
    float sn, cs; sincosf(ang, &sn, &cs);
    const float x1 = base[i], x2 = base[i + 128];
    const float o1 = x1 * cs - x2 * sn;
    const float o2 = x2 * cs + x1 * sn;
    bf16 h1, l1, h2, l2;
    split1(o1, h1, l1); split1(o2, h2, l2);
    oh[oo + i]       = h1;  ol[oo + i]       = l1;
    oh[oo + i + 128] = h2;  ol[oo + i + 128] = l2;
}

// ---------------------------------------------------------------------------
// Flash attention, bf16-split MMAs + ldmatrix.
// 2 full syncs per iter: V(kt) issued after sync B (hides under S-MMA),
// K(kt+1) issued after sync F (hides under PV-MMA; F proves all warps done
// reading K). In-register softmax (shfl + pair-warp exchange).
// ---------------------------------------------------------------------------
#define AQ_LD 264
#define AP_LD 72
#define AQ_HALVES (64 * AQ_LD)    // 16896 (per plane, Q and K tiles)
#define AV_HALVES (256 * AP_LD)   // 18432 (per plane, V tile)
#define APB_HALVES (64 * AP_LD)   // 4608  (per plane, P tile)

#define ATT_SMEM_BYTES ((4*AQ_HALVES + 2*AV_HALVES + 2*APB_HALVES) * 2 + (3*64 + 256) * 4)

__global__ __launch_bounds__(256, 1) void attn_mma_kernel(
    const bf16* __restrict__ qh, const bf16* __restrict__ ql,
    const bf16* __restrict__ kh, const bf16* __restrict__ kl,
    const bf16* __restrict__ vth, const bf16* __restrict__ vtl,
    bf16* __restrict__ ath, bf16* __restrict__ atl)
{
    extern __shared__ char smraw[];
    bf16* Qh = (bf16*)smraw;
    bf16* Ql = Qh + AQ_HALVES;
    bf16* Kh = Ql + AQ_HALVES;
    bf16* Kl = Kh + AQ_HALVES;
    bf16* Vh = Kl + AQ_HALVES;
    bf16* Vl = Vh + AV_HALVES;
    bf16* Ph = Vl + AV_HALVES;
    bf16* Pl = Ph + APB_HALVES;
    float* Ms = (float*)(Pl + APB_HALVES);
    float* Ls = Ms + 64;
    float* Cr = Ls + 64;
    float* Mx = Cr + 64;    // [128] pair-warp max exchange
    float* Sx = Mx + 128;   // [128] pair-warp sum exchange

    const int qt = (int)gridDim.x - 1 - (int)blockIdx.x;  // heavy tiles first
    const int h  = blockIdx.y;
    const int b  = blockIdx.z;
    const int tid = threadIdx.x;
    const int wid = tid >> 5, lane = tid & 31;
    const int g = lane >> 2, tg = lane & 3;
    const int m8 = lane >> 3, ri = lane & 7;
    const int wm  = (wid & 3) * 16;
    const int wn2 = (wid >> 2) * 32;
    const int wd  = (wid >> 2) * 128;
    const int half = wid >> 2;
    const int barid = (wid & 3) + 1;
    const int q0 = qt * 64;
    const float scale = 0.0625f;

    // prologue: Q tile (group) then K(0) tile (group)
    {
        #pragma unroll
        for (int j = 0; j < 8; j++) {
            const int c = tid + 256 * j;
            const int r = c >> 5, cc = (c & 31) * 8;
            const size_t go = (size_t)(b * S_ + q0 + r) * QKDIM_ + h * HD_ + cc;
            cpasync16(Qh + r * AQ_LD + cc, qh + go);
            cpasync16(Ql + r * AQ_LD + cc, ql + go);
        }
        cpcommit();
        #pragma unroll
        for (int j = 0; j < 8; j++) {
            const int c = tid + 256 * j;
            const int r = c >> 5, cc = (c & 31) * 8;
            const size_t go = (size_t)(b * S_ + r) * HD_ + cc;
            cpasync16(Kh + r * AQ_LD + cc, kh + go);
            cpasync16(Kl + r * AQ_LD + cc, kl + go);
        }
        cpcommit();
    }
    if (tid < 64) { Ms[tid] = -INFINITY; Ls[tid] = 0.f; Cr[tid] = 0.f; }

    float oc[16][4] = {};

    for (int kt = 0; kt <= qt; ++kt) {
        const int k0 = kt * 64;
        cpwait<0>();       // K(kt) (and Q on first iter) landed
        __syncthreads();   // B: K visible; PV(kt-1) done with V and P buffers

        // Issue V(kt) load now — hidden under S-MMA.
        #pragma unroll
        for (int j = 0; j < 8; j++) {
            const int c = tid + 256 * j;
            const int r = c >> 3, cc = (c & 7) * 8;
            const size_t go = (size_t)b * HD_ * S_ + (size_t)r * S_ + k0 + cc;
            cpasync16(Vh + r * AP_LD + cc, vth + go);
            cpasync16(Vl + r * AP_LD + cc, vtl + go);
        }
        cpcommit();        // group V

        // S = Q @ K^T via 3-MMA split (ldmatrix fragments)
        float sc[4][4] = {};
        #pragma unroll
        for (int kk = 0; kk < 256; kk += 16) {
            uint32_t ah[4], al[4];
            {
                const int ao = (wm + (m8 & 1) * 8 + ri) * AQ_LD + kk + (m8 >> 1) * 8;
                ldsm_x4(ah, Qh + ao);
                ldsm_x4(al, Ql + ao);
            }
            uint32_t bh[2][4], bl[2][4];
            #pragma unroll
            for (int p = 0; p < 2; p++) {
                const int bo = (wn2 + p * 16 + (m8 >> 1) * 8 + ri) * AQ_LD + kk + (m8 & 1) * 8;
                ldsm_x4(bh[p], Kh + bo);
                ldsm_x4(bl[p], Kl + bo);
            }
            #pragma unroll
            for (int p = 0; p < 2; p++)
                #pragma unroll
                for (int sub = 0; sub < 2; sub++) {
                    const int nt = p * 2 + sub;
                    mma16816(sc[nt], ah, bh[p][sub*2], bh[p][sub*2+1]);
                    mma16816(sc[nt], ah, bl[p][sub*2], bl[p][sub*2+1]);
                    mma16816(sc[nt], al, bh[p][sub*2], bh[p][sub*2+1]);
                }
        }

        // scale + causal mask in registers
        const int r0g = q0 + wm + g;
        const int r1g = r0g + 8;
        #pragma unroll
        for (int nt = 0; nt < 4; nt++) {
            const int col = k0 + wn2 + nt * 8 + tg * 2;
            sc[nt][0] = (col     > r0g) ? -1e30f : sc[nt][0] * scale;
            sc[nt][1] = (col + 1 > r0g) ? -1e30f : sc[nt][1] * scale;
            sc[nt][2] = (col     > r1g) ? -1e30f : sc[nt][2] * scale;
            sc[nt][3] = (col + 1 > r1g) ? -1e30f : sc[nt][3] * scale;
        }

        // In-register softmax. Rows r0=wm+g, r1=r0+8; 8 cols/row per thread.
        const int lr0 = wm + g, lr1 = lr0 + 8;
        float mx0 = -INFINITY, mx1 = -INFINITY;
        #pragma unroll
        for (int nt = 0; nt < 4; nt++) {
            mx0 = fmaxf(mx0, fmaxf(sc[nt][0], sc[nt][1]));
            mx1 = fmaxf(mx1, fmaxf(sc[nt][2], sc[nt][3]));
        }
        mx0 = fmaxf(mx0, __shfl_xor_sync(0xffffffffu, mx0, 1));
        mx0 = fmaxf(mx0, __shfl_xor_sync(0xffffffffu, mx0, 2));
        mx1 = fmaxf(mx1, __shfl_xor_sync(0xffffffffu, mx1, 1));
        mx1 = fmaxf(mx1, __shfl_xor_sync(0xffffffffu, mx1, 2));
        if (tg == 0) { Mx[half * 64 + lr0] = mx0; Mx[half * 64 + lr1] = mx1; }
        asm volatile("bar.sync %0, 64;" :: "r"(barid) : "memory");   // D (pair)

        const float mo0 = Ms[lr0], mo1 = Ms[lr1];
        const float mn0 = fmaxf(fmaxf(Mx[lr0], Mx[64 + lr0]), mo0);
        const float mn1 = fmaxf(fmaxf(Mx[lr1], Mx[64 + lr1]), mo1);
        float sum0 = 0.f, sum1 = 0.f;
        #pragma unroll
        for (int nt = 0; nt < 4; nt++) {
            const int colL = wn2 + nt * 8 + tg * 2;
            const float p0 = __expf(sc[nt][0] - mn0);
            const float p1 = __expf(sc[nt][1] - mn0);
            const float p2 = __expf(sc[nt][2] - mn1);
            const float p3 = __expf(sc[nt][3] - mn1);
            sum0 += p0 + p1; sum1 += p2 + p3;
            bf16 hb0,lb0,hb1,lb1,hb2,lb2,hb3,lb3;
            split1(p0,hb0,lb0); split1(p1,hb1,lb1);
            split1(p2,hb2,lb2); split1(p3,hb3,lb3);
            __nv_bfloat162 t;
            t.x=hb0; t.y=hb1; *(__nv_bfloat162*)(Ph + lr0 * AP_LD + colL) = t;
            t.x=lb0; t.y=lb1; *(__nv_bfloat162*)(Pl + lr0 * AP_LD + colL) = t;
            t.x=hb2; t.y=hb3; *(__nv_bfloat162*)(Ph + lr1 * AP_LD + colL) = t;
            t.x=lb2; t.y=lb3; *(__nv_bfloat162*)(Pl + lr1 * AP_LD + colL) = t;
        }
        sum0 += __shfl_xor_sync(0xffffffffu, sum0, 1);
        sum0 += __shfl_xor_sync(0xffffffffu, sum0, 2);
        sum1 += __shfl_xor_sync(0xffffffffu, sum1, 1);
        sum1 += __shfl_xor_sync(0xffffffffu, sum1, 2);
        if (tg == 0) { Sx[half * 64 + lr0] = sum0; Sx[half * 64 + lr1] = sum1; }
        asm volatile("bar.sync %0, 64;" :: "r"(barid) : "memory");   // E (pair)

        // one thread per row (warps 0-3, lanes 0-15) updates running state
        if (wid < 4 && lane < 16) {
            const int row = wm + lane;
            const float mo = Ms[row];
            const float mn = fmaxf(fmaxf(Mx[row], Mx[64 + row]), mo);
            const float corr = (mo == -INFINITY) ? 0.f : __expf(mo - mn);
            Ls[row] = Ls[row] * corr + Sx[row] + Sx[64 + row];
            Ms[row] = mn;
            Cr[row] = corr;
        }
        cpwait<0>();       // V(kt) landed (only group in flight)
        __syncthreads();   // F: V + Ph/Pl + state visible; all warps past S-MMA

        // Issue K(kt+1) load — hidden under PV-MMA. Safe: F proved all warps
        // finished reading K(kt).
        if (kt < qt) {
            const int kn = k0 + 64;
            #pragma unroll
            for (int j = 0; j < 8; j++) {
                const int c = tid + 256 * j;
                const int r = c >> 5, cc = (c & 31) * 8;
                const size_t go = (size_t)(b * S_ + kn + r) * HD_ + cc;
                cpasync16(Kh + r * AQ_LD + cc, kh + go);
                cpasync16(Kl + r * AQ_LD + cc, kl + go);
            }
            cpcommit();    // group K(kt+1)
        }

        // Rescale accumulator, then O += P @ V (3-MMA split, ldmatrix)
        const float cr0 = Cr[wm + g], cr1 = Cr[wm + g + 8];
        #pragma unroll
        for (int nt = 0; nt < 16; nt++) {
            oc[nt][0] *= cr0; oc[nt][1] *= cr0;
            oc[nt][2] *= cr1; oc[nt][3] *= cr1;
        }
        #pragma unroll
        for (int kk = 0; kk < 64; kk += 16) {
            uint32_t pa[4], pl_[4];
            {
                const int ao = (wm + (m8 & 1) * 8 + ri) * AP_LD + kk + (m8 >> 1) * 8;
                ldsm_x4(pa,  Ph + ao);
                ldsm_x4(pl_, Pl + ao);
            }
            #pragma unroll
            for (int p = 0; p < 8; p++) {
                uint32_t bh[4], bl[4];
                const int bo = (wd + p * 16 + (m8 >> 1) * 8 + ri) * AP_LD + kk + (m8 & 1) * 8;
                ldsm_x4(bh, Vh + bo);
                ldsm_x4(bl, Vl + bo);
                #pragma unroll
                for (int sub = 0; sub < 2; sub++) {
                    const int nt = p * 2 + sub;
                    mma16816(oc[nt], pa,  bh[sub*2], bh[sub*2+1]);
                    mma16816(oc[nt], pa,  bl[sub*2], bl[sub*2+1]);
                    mma16816(oc[nt], pl_, bh[sub*2], bh[sub*2+1]);
                }
            }
        }
    }

    const float inv0 = 1.f / Ls[wm + g];
    const float inv1 = 1.f / Ls[wm + g + 8];
    #pragma unroll
    for (int nt = 0; nt < 16; nt++) {
        const int d = wd + nt * 8 + tg * 2;
        const size_t base0 = (size_t)(b * S_ + q0 + wm + g) * QKDIM_ + h * HD_ + d;
        const size_t base1 = base0 + 8 * QKDIM_;
        const float v0 = oc[nt][0] * inv0, v1 = oc[nt][1] * inv0;
        const float v2 = oc[nt][2] * inv1, v3 = oc[nt][3] * inv1;
        bf16 h0,l0,h1,l1,h2,l2,h3,l3;
        split1(v0,h0,l0); split1(v1,h1,l1); split1(v2,h2,l2); split1(v3,h3,l3);
        __nv_bfloat162 t;
        t.x=h0; t.y=h1; *(__nv_bfloat162*)(ath + base0) = t;
        t.x=l0; t.y=l1; *(__nv_bfloat162*)(atl + base0) = t;
        t.x=h2; t.y=h3; *(__nv_bfloat162*)(ath + base1) = t;
        t.x=l2; t.y=l3; *(__nv_bfloat162*)(atl + base1) = t;
    }
}

// ---------------------------------------------------------------------------
// Launch
// Inputs: 0=hidden_states 1=attention_mask(unused) 2=position_ids
//         3=Wq 4=Wk 5=Wv 6=Wo
// ---------------------------------------------------------------------------
extern "C" void kernel_launch(void* const* d_in, const int* in_sizes, int n_in,
                              void* d_out, int out_size) {
    (void)in_sizes; (void)n_in; (void)out_size;
    const float* hs  = (const float*)d_in[0];
    const int*   pos = (const int*)  d_in[2];
    const float* Wq  = (const float*)d_in[3];
    const float* Wk  = (const float*)d_in[4];
    const float* Wv  = (const float*)d_in[5];
    const float* Wo  = (const float*)d_in[6];
    float* out = (float*)d_out;

    float *qkv;
    bf16 *hsh,*hsl,*qh,*ql,*kh,*kl,*vth,*vtl,*ath,*atl;
    bf16 *wallh,*walll,*woh,*wol;
    cudaGetSymbolAddress((void**)&qkv, g_qkv);
    cudaGetSymbolAddress((void**)&hsh, g_hsh); cudaGetSymbolAddress((void**)&hsl, g_hsl);
    cudaGetSymbolAddress((void**)&qh,  g_qh);  cudaGetSymbolAddress((void**)&ql,  g_ql);
    cudaGetSymbolAddress((void**)&kh,  g_kh);  cudaGetSymbolAddress((void**)&kl,  g_kl);
    cudaGetSymbolAddress((void**)&vth, g_vth); cudaGetSymbolAddress((void**)&vtl, g_vtl);
    cudaGetSymbolAddress((void**)&ath, g_ath); cudaGetSymbolAddress((void**)&atl, g_atl);
    cudaGetSymbolAddress((void**)&wallh, g_wallh); cudaGetSymbolAddress((void**)&walll, g_walll);
    cudaGetSymbolAddress((void**)&woh, g_woh); cudaGetSymbolAddress((void**)&wol, g_wol);

    cudaFuncSetAttribute(gemm_bf16s,
        cudaFuncAttributeMaxDynamicSharedMemorySize, GEMM_SMEM);
    cudaFuncSetAttribute(attn_mma_kernel,
        cudaFuncAttributeMaxDynamicSharedMemorySize, ATT_SMEM_BYTES);

    const dim3 tb(32, 8);

    // Split hidden states; transpose+split weights (QKV fused into one launch)
    split_strided_kernel<<<(M_ * HID_ / 4 + 255) / 256, 256>>>(
        hs, hsh, hsl, M_ * HID_, 11, HID_);
    wqkv_transpose_kernel<<<dim3(NQKV_ / 32, HID_ / 32), tb>>>(
        Wq, Wk, Wv, wallh, walll);
    transpose_split_kernel<<<dim3(64, 64, 1), tb>>>(
        Wo, woh, wol, HID_, 0, QKDIM_, 0);

    // Fused QKV projection (tensor core): C[4096][2560]
    gemm_bf16s<<<dim3(NQKV_ / 128, M_ / 128), 256, GEMM_SMEM>>>(
        hsh, hsl, wallh, walll, qkv, M_, NQKV_, HID_);

    // Fused RoPE + split: qkv -> split Q/K directly
    {
        const int total = B_ * S_ * NH_ * (HD_ / 2) + B_ * S_ * (HD_ / 2);
        rope_split_kernel<<<(total + 255) / 256, 256>>>(qkv, pos, qh, ql, kh, kl);
    }

    // Transpose+split V per batch
    transpose_split_kernel<<<dim3(8, 64, B_), tb>>>(
        qkv + QKDIM_ + HD_, vth, vtl,
        NQKV_, (size_t)S_ * NQKV_, S_, (size_t)HD_ * S_);

    // Attention (tensor core flash)
    attn_mma_kernel<<<dim3(S_ / 64, NH_, B_), 256, ATT_SMEM_BYTES>>>(
        qh, ql, kh, kl, vth, vtl, ath, atl);

    // Output projection (tensor core)
    gemm_bf16s<<<dim3(HID_ / 128, M_ / 128), 256, GEMM_SMEM>>>(
        ath, atl, woh, wol, out, M_, HID_, HID_);
}

// round 14
// speedup vs baseline: 1.0147x; 1.0100x over previous
#include <cuda_runtime.h>
#include <cuda_bf16.h>
#include <math.h>
#include <stdint.h>

// Problem constants
#define B_ 2
#define S_ 2048
#define HID_ 2048
#define NH_ 8
#define HD_ 256
#define M_ 4096           // B*S
#define QKDIM_ (NH_*HD_)  // 2048
#define NQKV_ 2560        // 2048 (Q) + 256 (K) + 256 (V)

typedef __nv_bfloat16 bf16;

// ---------------------------------------------------------------------------
// Scratch (device globals: allocation-free per harness rules)
// ---------------------------------------------------------------------------
__device__ float g_qkv[M_ * NQKV_];                         // fused QKV output (fp32)

__device__ bf16 g_hsh[M_ * HID_],  g_hsl[M_ * HID_];        // split hidden_states
__device__ bf16 g_qh [M_ * QKDIM_], g_ql [M_ * QKDIM_];     // split Q (post-RoPE)
__device__ bf16 g_kh [M_ * HD_],   g_kl [M_ * HD_];         // split K
__device__ bf16 g_vth[B_ * HD_ * S_], g_vtl[B_ * HD_ * S_]; // V transposed [b][d][s]
__device__ bf16 g_ath[M_ * QKDIM_], g_atl[M_ * QKDIM_];     // split attention output

__device__ bf16 g_wallh[NQKV_ * HID_];                      // fused [Wq;Wk;Wv]^T hi
__device__ bf16 g_walll[NQKV_ * HID_];                      // fused lo
__device__ bf16 g_woh[QKDIM_ * HID_], g_wol[QKDIM_ * HID_];

// ---------------------------------------------------------------------------
// Helpers
// ---------------------------------------------------------------------------
__device__ __forceinline__ void split1(float x, bf16& h, bf16& l) {
    h = __float2bfloat16(x);
    l = __float2bfloat16(x - __bfloat162float(h));
}

__device__ __forceinline__ void mma16816(float (&d)[4], const uint32_t (&a)[4],
                                         uint32_t b0, uint32_t b1) {
    asm volatile(
        "mma.sync.aligned.m16n8k16.row.col.f32.bf16.bf16.f32 "
        "{%0,%1,%2,%3}, {%4,%5,%6,%7}, {%8,%9}, {%0,%1,%2,%3};\n"
        : "+f"(d[0]), "+f"(d[1]), "+f"(d[2]), "+f"(d[3])
        : "r"(a[0]), "r"(a[1]), "r"(a[2]), "r"(a[3]), "r"(b0), "r"(b1));
}

__device__ __forceinline__ void ldsm_x4(uint32_t (&r)[4], const bf16* p) {
    uint32_t a = (uint32_t)__cvta_generic_to_shared(p);
    asm volatile("ldmatrix.sync.aligned.m8n8.x4.shared.b16 {%0,%1,%2,%3}, [%4];\n"
        : "=r"(r[0]), "=r"(r[1]), "=r"(r[2]), "=r"(r[3]) : "r"(a));
}

__device__ __forceinline__ void cpasync16(bf16* s, const bf16* g) {
    uint32_t sa = (uint32_t)__cvta_generic_to_shared(s);
    asm volatile("cp.async.cg.shared.global [%0], [%1], 16;\n" :: "r"(sa), "l"(g));
}
__device__ __forceinline__ void cpcommit() {
    asm volatile("cp.async.commit_group;\n");
}
template<int N> __device__ __forceinline__ void cpwait() {
    asm volatile("cp.async.wait_group %0;\n" :: "n"(N));
}

// ---------------------------------------------------------------------------
// Elementwise split with strided source.
// ---------------------------------------------------------------------------
__global__ void split_strided_kernel(const float* __restrict__ in,
                                     bf16* __restrict__ oh, bf16* __restrict__ ol,
                                     int n, int colshift, int ldin) {
    int i = (blockIdx.x * blockDim.x + threadIdx.x) * 4;
    if (i >= n) return;
    int r = i >> colshift;
    int c = i & ((1 << colshift) - 1);
    float4 v = *(const float4*)(in + (size_t)r * ldin + c);
    bf16 h0,l0,h1,l1,h2,l2,h3,l3;
    split1(v.x,h0,l0); split1(v.y,h1,l1); split1(v.z,h2,l2); split1(v.w,h3,l3);
    __nv_bfloat162 a, b;
    a.x=h0; a.y=h1; b.x=h2; b.y=h3;
    *(__nv_bfloat162*)(oh+i)   = a; *(__nv_bfloat162*)(oh+i+2) = b;
    a.x=l0; a.y=l1; b.x=l2; b.y=l3;
    *(__nv_bfloat162*)(ol+i)   = a; *(__nv_bfloat162*)(ol+i+2) = b;
}

// ---------------------------------------------------------------------------
// Tiled transpose + split (generic).
// ---------------------------------------------------------------------------
__global__ void transpose_split_kernel(const float* __restrict__ in,
                                       bf16* __restrict__ oh, bf16* __restrict__ ol,
                                       int ldin, size_t bsIn, int ldout, size_t bsOut) {
    __shared__ float t[32][33];
    const float* ip = in + (size_t)blockIdx.z * bsIn;
    bf16* ohp = oh + (size_t)blockIdx.z * bsOut;
    bf16* olp = ol + (size_t)blockIdx.z * bsOut;
    const int r0 = blockIdx.y * 32, c0 = blockIdx.x * 32;
    #pragma unroll
    for (int i = 0; i < 4; i++) {
        int r = threadIdx.y + i * 8;
        t[r][threadIdx.x] = ip[(size_t)(r0 + r) * ldin + c0 + threadIdx.x];
    }
    __syncthreads();
    #pragma unroll
    for (int i = 0; i < 4; i++) {
        int c = threadIdx.y + i * 8;
        float v = t[threadIdx.x][c];
        bf16 h, l; split1(v, h, l);
        size_t o = (size_t)(c0 + c) * ldout + r0 + threadIdx.x;
        ohp[o] = h; olp[o] = l;
    }
}

// ---------------------------------------------------------------------------
// Fused QKV weight transpose+split: out [2560][2048] = [Wq^T; Wk^T; Wv^T].
// ---------------------------------------------------------------------------
__global__ void wqkv_transpose_kernel(const float* __restrict__ Wq,
                                      const float* __restrict__ Wk,
                                      const float* __restrict__ Wv,
                                      bf16* __restrict__ oh, bf16* __restrict__ ol) {
    __shared__ float t[32][33];
    const int c0 = blockIdx.x * 32;   // output row block (N dim, 0..2559)
    const int r0 = blockIdx.y * 32;   // HID block
    const float* src; int ldin, cbase;
    if (c0 < QKDIM_)            { src = Wq; ldin = QKDIM_; cbase = c0; }
    else if (c0 < QKDIM_ + HD_) { src = Wk; ldin = HD_;    cbase = c0 - QKDIM_; }
    else                        { src = Wv; ldin = HD_;    cbase = c0 - QKDIM_ - HD_; }
    #pragma unroll
    for (int i = 0; i < 4; i++) {
        int r = threadIdx.y + i * 8;
        t[r][threadIdx.x] = src[(size_t)(r0 + r) * ldin + cbase + threadIdx.x];
    }
    __syncthreads();
    #pragma unroll
    for (int i = 0; i < 4; i++) {
        int c = threadIdx.y + i * 8;
        float v = t[threadIdx.x][c];
        bf16 h, l; split1(v, h, l);
        size_t o = (size_t)(c0 + c) * HID_ + r0 + threadIdx.x;
        oh[o] = h; ol[o] = l;
    }
}

// ---------------------------------------------------------------------------
// GEMM (wide): C[M,N] = A@B^T, tile 128x128, 2 CTAs/SM. Used for O-proj
// (grid 512 -> 1.73 waves of 296, 86% busy).
// ---------------------------------------------------------------------------
#define GLDA 40                    // 32 + 8 halves pad (80B row: LDSM conflict-free)
#define PLANEH (128 * GLDA)        // 5120 halves per plane
#define STAGEH (4 * PLANEH)        // Ah, Al, Bh, Bl
#define GEMM_SMEM (2 * STAGEH * 2) // 2 stages: 81920 bytes

__global__ __launch_bounds__(256, 2) void gemm_bf16s(
    const bf16* __restrict__ Ah, const bf16* __restrict__ Al,
    const bf16* __restrict__ Bh, const bf16* __restrict__ Bl,
    float* __restrict__ C, int M, int N, int K)
{
    extern __shared__ bf16 sm[];
    const int tid = threadIdx.x;
    const int wid = tid >> 5, lane = tid & 31;
    const int g = lane >> 2, tg = lane & 3;
    const int m8 = lane >> 3, ri = lane & 7;
    const int wm = (wid & 3) * 32;
    const int wn = (wid >> 2) * 64;
    const int row0 = blockIdx.y * 128;
    const int col0 = blockIdx.x * 128;

    const int lr = tid >> 1;
    const int lc = (tid & 1) * 16;
    const bf16* gA  = Ah + (size_t)(row0 + lr) * K + lc;
    const bf16* gAl = Al + (size_t)(row0 + lr) * K + lc;
    const bf16* gB  = Bh + (size_t)(col0 + lr) * K + lc;
    const bf16* gBl = Bl + (size_t)(col0 + lr) * K + lc;
    const int soff = lr * GLDA + lc;

    float acc[2][8][4] = {};
    const int nk = K / 32;

    auto load_stage = [&](int chunk, int st) {
        const int k0 = chunk * 32;
        bf16* s = sm + st * STAGEH + soff;
        cpasync16(s,            gA  + k0);  cpasync16(s + 8,            gA  + k0 + 8);
        cpasync16(s + PLANEH,   gAl + k0);  cpasync16(s + PLANEH + 8,   gAl + k0 + 8);
        cpasync16(s + 2*PLANEH, gB  + k0);  cpasync16(s + 2*PLANEH + 8, gB  + k0 + 8);
        cpasync16(s + 3*PLANEH, gBl + k0);  cpasync16(s + 3*PLANEH + 8, gBl + k0 + 8);
        cpcommit();
    };

    load_stage(0, 0);

    for (int i = 0; i < nk; i++) {
        cpwait<0>();
        __syncthreads();
        if (i + 1 < nk) load_stage(i + 1, (i + 1) & 1);

        const bf16* pAh = sm + (i & 1) * STAGEH;
        const bf16* pAl = pAh + PLANEH;
        const bf16* pBh = pAh + 2 * PLANEH;
        const bf16* pBl = pAh + 3 * PLANEH;

        #pragma unroll
        for (int kk = 0; kk < 32; kk += 16) {
            uint32_t ah[2][4], al[2][4];
            #pragma unroll
            for (int mt = 0; mt < 2; mt++) {
                const int ao = (wm + mt * 16 + (m8 & 1) * 8 + ri) * GLDA + kk + (m8 >> 1) * 8;
                ldsm_x4(ah[mt], pAh + ao);
                ldsm_x4(al[mt], pAl + ao);
            }
            uint32_t bh[4][4], bl[4][4];
            #pragma unroll
            for (int p = 0; p < 4; p++) {
                const int bo = (wn + p * 16 + (m8 >> 1) * 8 + ri) * GLDA + kk + (m8 & 1) * 8;
                ldsm_x4(bh[p], pBh + bo);
                ldsm_x4(bl[p], pBl + bo);
            }
            #pragma unroll
            for (int p = 0; p < 4; p++)
                #pragma unroll
                for (int sub = 0; sub < 2; sub++) {
                    const int nt = p * 2 + sub;
                    const uint32_t h0 = bh[p][sub*2], h1 = bh[p][sub*2+1];
                    const uint32_t l0 = bl[p][sub*2], l1 = bl[p][sub*2+1];
                    #pragma unroll
                    for (int mt = 0; mt < 2; mt++) {
                        mma16816(acc[mt][nt], ah[mt], h0, h1);
                        mma16816(acc[mt][nt], ah[mt], l0, l1);
                        mma16816(acc[mt][nt], al[mt], h0, h1);
                    }
                }
        }
    }

    #pragma unroll
    for (int mt = 0; mt < 2; mt++)
        #pragma unroll
        for (int nt = 0; nt < 8; nt++) {
            const int r  = row0 + wm + mt * 16 + g;
            const int cn = col0 + wn + nt * 8 + tg * 2;
            float2 v01; v01.x = acc[mt][nt][0]; v01.y = acc[mt][nt][1];
            float2 v23; v23.x = acc[mt][nt][2]; v23.y = acc[mt][nt][3];
            *(float2*)(C + (size_t)r * N + cn)       = v01;
            *(float2*)(C + (size_t)(r + 8) * N + cn) = v23;
        }
}

// ---------------------------------------------------------------------------
// GEMM (narrow): C[M,N] = A@B^T, tile 128x64, warp tile 32x32, 3 CTAs/SM.
// Used for QKV (grid 1280 -> 2.88 waves of 444, 96% busy vs 72% for 128x128).
// smem/stage: Ah/Al 128x40, Bh/Bl 64x40 -> 30720 B; 2 stages = 61440 B.
// Each thread loads 6x16B per stage: A hi/lo 2 chunks each, B 2 chunks.
// ---------------------------------------------------------------------------
#define N64_APL (128 * GLDA)             // 5120 halves (A plane)
#define N64_BPL (64 * GLDA)              // 2560 halves (B plane)
#define N64_STAGEH (2 * N64_APL + 2 * N64_BPL)  // 15360 halves
#define N64_SMEM (2 * N64_STAGEH * 2)    // 61440 bytes

__global__ __launch_bounds__(256, 3) void gemm_bf16s_n64(
    const bf16* __restrict__ Ah, const bf16* __restrict__ Al,
    const bf16* __restrict__ Bh, const bf16* __restrict__ Bl,
    float* __restrict__ C, int M, int N, int K)
{
    extern __shared__ bf16 sm[];
    const int tid = threadIdx.x;
    const int wid = tid >> 5, lane = tid & 31;
    const int g = lane >> 2, tg = lane & 3;
    const int m8 = lane >> 3, ri = lane & 7;
    const int wm = (wid & 3) * 32;
    const int wn = (wid >> 2) * 32;
    const int row0 = blockIdx.y * 128;
    const int col0 = blockIdx.x * 64;

    // cp.async mapping:
    //  A: thread -> row tid>>1, 16-half chunk at (tid&1)*16; both planes.
    //  B: thread -> row tid>>2, plane (tid>>1)&1, 16-half chunk at (tid&1)*16.
    const int alr = tid >> 1;
    const int alc = (tid & 1) * 16;
    const int blr = tid >> 2;
    const int bpl = (tid >> 1) & 1;     // B plane (0=hi, 1=lo)
    const int blc = (tid & 1) * 16;
    const bf16* gA  = Ah + (size_t)(row0 + alr) * K + alc;
    const bf16* gAl = Al + (size_t)(row0 + alr) * K + alc;
    const bf16* gB  = (bpl ? Bl : Bh) + (size_t)(col0 + blr) * K + blc;
    const int aoff = alr * GLDA + alc;
    const int boff = 2 * N64_APL + bpl * N64_BPL + blr * GLDA + blc;

    float acc[2][4][4] = {};
    const int nk = K / 32;

    auto load_stage = [&](int chunk, int st) {
        const int k0 = chunk * 32;
        bf16* s = sm + st * N64_STAGEH;
        cpasync16(s + aoff,               gA  + k0);
        cpasync16(s + aoff + 8,           gA  + k0 + 8);
        cpasync16(s + N64_APL + aoff,     gAl + k0);
        cpasync16(s + N64_APL + aoff + 8, gAl + k0 + 8);
        cpasync16(s + boff,               gB  + k0);
        cpasync16(s + boff + 8,           gB  + k0 + 8);
        cpcommit();
    };

    load_stage(0, 0);

    for (int i = 0; i < nk; i++) {
        cpwait<0>();
        __syncthreads();
        if (i + 1 < nk) load_stage(i + 1, (i + 1) & 1);

        const bf16* pAh = sm + (i & 1) * N64_STAGEH;
        const bf16* pAl = pAh + N64_APL;
        const bf16* pBh = pAh + 2 * N64_APL;
        const bf16* pBl = pBh + N64_BPL;

        #pragma unroll
        for (int kk = 0; kk < 32; kk += 16) {
            uint32_t ah[2][4], al[2][4];
            #pragma unroll
            for (int mt = 0; mt < 2; mt++) {
                const int ao = (wm + mt * 16 + (m8 & 1) * 8 + ri) * GLDA + kk + (m8 >> 1) * 8;
                ldsm_x4(ah[mt], pAh + ao);
                ldsm_x4(al[mt], pAl + ao);
            }
            #pragma unroll
            for (int p = 0; p < 2; p++) {
                uint32_t bh[4], bl[4];
                const int bo = (wn + p * 16 + (m8 >> 1) * 8 + ri) * GLDA + kk + (m8 & 1) * 8;
                ldsm_x4(bh, pBh + bo);
                ldsm_x4(bl, pBl + bo);
                #pragma unroll
                for (int sub = 0; sub < 2; sub++) {
                    const int nt = p * 2 + sub;
                    const uint32_t h0 = bh[sub*2], h1 = bh[sub*2+1];
                    const uint32_t l0 = bl[sub*2], l1 = bl[sub*2+1];
                    #pragma unroll
                    for (int mt = 0; mt < 2; mt++) {
                        mma16816(acc[mt][nt], ah[mt], h0, h1);
                        mma16816(acc[mt][nt], ah[mt], l0, l1);
                        mma16816(acc[mt][nt], al[mt], h0, h1);
                    }
                }
            }
        }
    }

    #pragma unroll
    for (int mt = 0; mt < 2; mt++)
        #pragma unroll
        for (int nt = 0; nt < 4; nt++) {
            const int r  = row0 + wm + mt * 16 + g;
            const int cn = col0 + wn + nt * 8 + tg * 2;
            float2 v01; v01.x = acc[mt][nt][0]; v01.y = acc[mt][nt][1];
            float2 v23; v23.x = acc[mt][nt][2]; v23.y = acc[mt][nt][3];
            *(float2*)(C + (size_t)r * N + cn)       = v01;
            *(float2*)(C + (size_t)(r + 8) * N + cn) = v23;
        }
}

// ---------------------------------------------------------------------------
// Fused RoPE + split: reads fp32 pairs from qkv, rotates, writes split bf16
// directly into qh/ql (Q) and kh/kl (K).
// ---------------------------------------------------------------------------
__global__ void rope_split_kernel(const float* __restrict__ qkv,
                                  const int* __restrict__ pos,
                                  bf16* __restrict__ qh, bf16* __restrict__ ql,
                                  bf16* __restrict__ kh, bf16* __restrict__ kl)
{
    const int QP = B_ * S_ * NH_ * (HD_ / 2);
    const int KP = B_ * S_ * (HD_ / 2);
    int idx = blockIdx.x * blockDim.x + threadIdx.x;
    if (idx >= QP + KP) return;
    const float L2B = 13.28771237954945f;  // log2(10000)

    int i, bs;
    const float* base;
    bf16 *oh, *ol;
    size_t oo;
    if (idx < QP) {
        i  = idx & 127;
        const int h = (idx >> 7) & 7;
        bs = idx >> 10;
        base = qkv + (size_t)bs * NQKV_ + h * HD_;
        oo = (size_t)bs * QKDIM_ + h * HD_;
        oh = qh; ol = ql;
    } else {
        const int j = idx - QP;
        i  = j & 127;
        bs = j >> 7;
        base = qkv + (size_t)bs * NQKV_ + QKDIM_;
        oo = (size_t)bs * HD_;
        oh = kh; ol = kl;
    }
    const float inv = exp2f(-(float)(2 * i) * (L2B / 256.f));
    const float ang = (float)pos[bs] * inv;
    float sn, cs; sincosf(ang, &sn, &cs);
    const float x1 = base[i], x2 = base[i + 128];
    const float o1 = x1 * cs - x2 * sn;
    const float o2 = x2 * cs + x1 * sn;
    bf16 h1, l1, h2, l2;
    split1(o1, h1, l1); split1(o2, h2, l2);
    oh[oo + i]       = h1;  ol[oo + i]       = l1;
    oh[oo + i + 128] = h2;  ol[oo + i + 128] = l2;
}

// ---------------------------------------------------------------------------
// Flash attention, bf16-split MMAs + ldmatrix.  (unchanged from R12)
// ---------------------------------------------------------------------------
#define AQ_LD 264
#define AP_LD 72
#define AQ_HALVES (64 * AQ_LD)
#define AV_HALVES (256 * AP_LD)
#define APB_HALVES (64 * AP_LD)

#define ATT_SMEM_BYTES ((4*AQ_HALVES + 2*AV_HALVES + 2*APB_HALVES) * 2 + (3*64 + 256) * 4)

__global__ __launch_bounds__(256, 1) void attn_mma_kernel(
    const bf16* __restrict__ qh, const bf16* __restrict__ ql,
    const bf16* __restrict__ kh, const bf16* __restrict__ kl,
    const bf16* __restrict__ vth, const bf16* __restrict__ vtl,
    bf16* __restrict__ ath, bf16* __restrict__ atl)
{
    extern __shared__ char smraw[];
    bf16* Qh = (bf16*)smraw;
    bf16* Ql = Qh + AQ_HALVES;
    bf16* Kh = Ql + AQ_HALVES;
    bf16* Kl = Kh + AQ_HALVES;
    bf16* Vh = Kl + AQ_HALVES;
    bf16* Vl = Vh + AV_HALVES;
    bf16* Ph = Vl + AV_HALVES;
    bf16* Pl = Ph + APB_HALVES;
    float* Ms = (float*)(Pl + APB_HALVES);
    float* Ls = Ms + 64;
    float* Cr = Ls + 64;
    float* Mx = Cr + 64;
    float* Sx = Mx + 128;

    const int qt = (int)gridDim.x - 1 - (int)blockIdx.x;
    const int h  = blockIdx.y;
    const int b  = blockIdx.z;
    const int tid = threadIdx.x;
    const int wid = tid >> 5, lane = tid & 31;
    const int g = lane >> 2, tg = lane & 3;
    const int m8 = lane >> 3, ri = lane & 7;
    const int wm  = (wid & 3) * 16;
    const int wn2 = (wid >> 2) * 32;
    const int wd  = (wid >> 2) * 128;
    const int half = wid >> 2;
    const int barid = (wid & 3) + 1;
    const int q0 = qt * 64;
    const float scale = 0.0625f;

    {
        #pragma unroll
        for (int j = 0; j < 8; j++) {
            const int c = tid + 256 * j;
            const int r = c >> 5, cc = (c & 31) * 8;
            const size_t go = (size_t)(b * S_ + q0 + r) * QKDIM_ + h * HD_ + cc;
            cpasync16(Qh + r * AQ_LD + cc, qh + go);
            cpasync16(Ql + r * AQ_LD + cc, ql + go);
        }
        cpcommit();
        #pragma unroll
        for (int j = 0; j < 8; j++) {
            const int c = tid + 256 * j;
            const int r = c >> 5, cc = (c & 31) * 8;
            const size_t go = (size_t)(b * S_ + r) * HD_ + cc;
            cpasync16(Kh + r * AQ_LD + cc, kh + go);
            cpasync16(Kl + r * AQ_LD + cc, kl + go);
        }
        cpcommit();
    }
    if (tid < 64) { Ms[tid] = -INFINITY; Ls[tid] = 0.f; Cr[tid] = 0.f; }

    float oc[16][4] = {};

    for (int kt = 0; kt <= qt; ++kt) {
        const int k0 = kt * 64;
        cpwait<0>();
        __syncthreads();   // B

        #pragma unroll
        for (int j = 0; j < 8; j++) {
            const int c = tid + 256 * j;
            const int r = c >> 3, cc = (c & 7) * 8;
            const size_t go = (size_t)b * HD_ * S_ + (size_t)r * S_ + k0 + cc;
            cpasync16(Vh + r * AP_LD + cc, vth + go);
            cpasync16(Vl + r * AP_LD + cc, vtl + go);
        }
        cpcommit();

        float sc[4][4] = {};
        #pragma unroll
        for (int kk = 0; kk < 256; kk += 16) {
            uint32_t ah[4], al[4];
            {
                const int ao = (wm + (m8 & 1) * 8 + ri) * AQ_LD + kk + (m8 >> 1) * 8;
                ldsm_x4(ah, Qh + ao);
                ldsm_x4(al, Ql + ao);
            }
            uint32_t bh[2][4], bl[2][4];
            #pragma unroll
            for (int p = 0; p < 2; p++) {
                const int bo = (wn2 + p * 16 + (m8 >> 1) * 8 + ri) * AQ_LD + kk + (m8 & 1) * 8;
                ldsm_x4(bh[p], Kh + bo);
                ldsm_x4(bl[p], Kl + bo);
            }
            #pragma unroll
            for (int p = 0; p < 2; p++)
                #pragma unroll
                for (int sub = 0; sub < 2; sub++) {
                    const int nt = p * 2 + sub;
                    mma16816(sc[nt], ah, bh[p][sub*2], bh[p][sub*2+1]);
                    mma16816(sc[nt], ah, bl[p][sub*2], bl[p][sub*2+1]);
                    mma16816(sc[nt], al, bh[p][sub*2], bh[p][sub*2+1]);
                }
        }

        const int r0g = q0 + wm + g;
        const int r1g = r0g + 8;
        #pragma unroll
        for (int nt = 0; nt < 4; nt++) {
            const int col = k0 + wn2 + nt * 8 + tg * 2;
            sc[nt][0] = (col     > r0g) ? -1e30f : sc[nt][0] * scale;
            sc[nt][1] = (col + 1 > r0g) ? -1e30f : sc[nt][1] * scale;
            sc[nt][2] = (col     > r1g) ? -1e30f : sc[nt][2] * scale;
            sc[nt][3] = (col + 1 > r1g) ? -1e30f : sc[nt][3] * scale;
        }

        const int lr0 = wm + g, lr1 = lr0 + 8;
        float mx0 = -INFINITY, mx1 = -INFINITY;
        #pragma unroll
        for (int nt = 0; nt < 4; nt++) {
            mx0 = fmaxf(mx0, fmaxf(sc[nt][0], sc[nt][1]));
            mx1 = fmaxf(mx1, fmaxf(sc[nt][2], sc[nt][3]));
        }
        mx0 = fmaxf(mx0, __shfl_xor_sync(0xffffffffu, mx0, 1));
        mx0 = fmaxf(mx0, __shfl_xor_sync(0xffffffffu, mx0, 2));
        mx1 = fmaxf(mx1, __shfl_xor_sync(0xffffffffu, mx1, 1));
        mx1 = fmaxf(mx1, __shfl_xor_sync(0xffffffffu, mx1, 2));
        if (tg == 0) { Mx[half * 64 + lr0] = mx0; Mx[half * 64 + lr1] = mx1; }
        asm volatile("bar.sync %0, 64;" :: "r"(barid) : "memory");   // D

        const float mo0 = Ms[lr0], mo1 = Ms[lr1];
        const float mn0 = fmaxf(fmaxf(Mx[lr0], Mx[64 + lr0]), mo0);
        const float mn1 = fmaxf(fmaxf(Mx[lr1], Mx[64 + lr1]), mo1);
        float sum0 = 0.f, sum1 = 0.f;
        #pragma unroll
        for (int nt = 0; nt < 4; nt++) {
            const int colL = wn2 + nt * 8 + tg * 2;
            const float p0 = __expf(sc[nt][0] - mn0);
            const float p1 = __expf(sc[nt][1] - mn0);
            const float p2 = __expf(sc[nt][2] - mn1);
            const float p3 = __expf(sc[nt][3] - mn1);
            sum0 += p0 + p1; sum1 += p2 + p3;
            bf16 hb0,lb0,hb1,lb1,hb2,lb2,hb3,lb3;
            split1(p0,hb0,lb0); split1(p1,hb1,lb1);
            split1(p2,hb2,lb2); split1(p3,hb3,lb3);
            __nv_bfloat162 t;
            t.x=hb0; t.y=hb1; *(__nv_bfloat162*)(Ph + lr0 * AP_LD + colL) = t;
            t.x=lb0; t.y=lb1; *(__nv_bfloat162*)(Pl + lr0 * AP_LD + colL) = t;
            t.x=hb2; t.y=hb3; *(__nv_bfloat162*)(Ph + lr1 * AP_LD + colL) = t;
            t.x=lb2; t.y=lb3; *(__nv_bfloat162*)(Pl + lr1 * AP_LD + colL) = t;
        }
        sum0 += __shfl_xor_sync(0xffffffffu, sum0, 1);
        sum0 += __shfl_xor_sync(0xffffffffu, sum0, 2);
        sum1 += __shfl_xor_sync(0xffffffffu, sum1, 1);
        sum1 += __shfl_xor_sync(0xffffffffu, sum1, 2);
        if (tg == 0) { Sx[half * 64 + lr0] = sum0; Sx[half * 64 + lr1] = sum1; }
        asm volatile("bar.sync %0, 64;" :: "r"(barid) : "memory");   // E

        if (wid < 4 && lane < 16) {
            const int row = wm + lane;
            const float mo = Ms[row];
            const float mn = fmaxf(fmaxf(Mx[row], Mx[64 + row]), mo);
            const float corr = (mo == -INFINITY) ? 0.f : __expf(mo - mn);
            Ls[row] = Ls[row] * corr + Sx[row] + Sx[64 + row];
            Ms[row] = mn;
            Cr[row] = corr;
        }
        cpwait<0>();
        __syncthreads();   // F

        if (kt < qt) {
            const int kn = k0 + 64;
            #pragma unroll
            for (int j = 0; j < 8; j++) {
                const int c = tid + 256 * j;
                const int r = c >> 5, cc = (c & 31) * 8;
                const size_t go = (size_t)(b * S_ + kn + r) * HD_ + cc;
                cpasync16(Kh + r * AQ_LD + cc, kh + go);
                cpasync16(Kl + r * AQ_LD + cc, kl + go);
            }
            cpcommit();
        }

        const float cr0 = Cr[wm + g], cr1 = Cr[wm + g + 8];
        #pragma unroll
        for (int nt = 0; nt < 16; nt++) {
            oc[nt][0] *= cr0; oc[nt][1] *= cr0;
            oc[nt][2] *= cr1; oc[nt][3] *= cr1;
        }
        #pragma unroll
        for (int kk = 0; kk < 64; kk += 16) {
            uint32_t pa[4], pl_[4];
            {
                const int ao = (wm + (m8 & 1) * 8 + ri) * AP_LD + kk + (m8 >> 1) * 8;
                ldsm_x4(pa,  Ph + ao);
                ldsm_x4(pl_, Pl + ao);
            }
            #pragma unroll
            for (int p = 0; p < 8; p++) {
                uint32_t bh[4], bl[4];
                const int bo = (wd + p * 16 + (m8 >> 1) * 8 + ri) * AP_LD + kk + (m8 & 1) * 8;
                ldsm_x4(bh, Vh + bo);
                ldsm_x4(bl, Vl + bo);
                #pragma unroll
                for (int sub = 0; sub < 2; sub++) {
                    const int nt = p * 2 + sub;
                    mma16816(oc[nt], pa,  bh[sub*2], bh[sub*2+1]);
                    mma16816(oc[nt], pa,  bl[sub*2], bl[sub*2+1]);
                    mma16816(oc[nt], pl_, bh[sub*2], bh[sub*2+1]);
                }
            }
        }
    }

    const float inv0 = 1.f / Ls[wm + g];
    const float inv1 = 1.f / Ls[wm + g + 8];
    #pragma unroll
    for (int nt = 0; nt < 16; nt++) {
        const int d = wd + nt * 8 + tg * 2;
        const size_t base0 = (size_t)(b * S_ + q0 + wm + g) * QKDIM_ + h * HD_ + d;
        const size_t base1 = base0 + 8 * QKDIM_;
        const float v0 = oc[nt][0] * inv0, v1 = oc[nt][1] * inv0;
        const float v2 = oc[nt][2] * inv1, v3 = oc[nt][3] * inv1;
        bf16 h0,l0,h1,l1,h2,l2,h3,l3;
        split1(v0,h0,l0); split1(v1,h1,l1); split1(v2,h2,l2); split1(v3,h3,l3);
        __nv_bfloat162 t;
        t.x=h0; t.y=h1; *(__nv_bfloat162*)(ath + base0) = t;
        t.x=l0; t.y=l1; *(__nv_bfloat162*)(atl + base0) = t;
        t.x=h2; t.y=h3; *(__nv_bfloat162*)(ath + base1) = t;
        t.x=l2; t.y=l3; *(__nv_bfloat162*)(atl + base1) = t;
    }
}

// ---------------------------------------------------------------------------
// Launch
// Inputs: 0=hidden_states 1=attention_mask(unused) 2=position_ids
//         3=Wq 4=Wk 5=Wv 6=Wo
// ---------------------------------------------------------------------------
extern "C" void kernel_launch(void* const* d_in, const int* in_sizes, int n_in,
                              void* d_out, int out_size) {
    (void)in_sizes; (void)n_in; (void)out_size;
    const float* hs  = (const float*)d_in[0];
    const int*   pos = (const int*)  d_in[2];
    const float* Wq  = (const float*)d_in[3];
    const float* Wk  = (const float*)d_in[4];
    const float* Wv  = (const float*)d_in[5];
    const float* Wo  = (const float*)d_in[6];
    float* out = (float*)d_out;

    float *qkv;
    bf16 *hsh,*hsl,*qh,*ql,*kh,*kl,*vth,*vtl,*ath,*atl;
    bf16 *wallh,*walll,*woh,*wol;
    cudaGetSymbolAddress((void**)&qkv, g_qkv);
    cudaGetSymbolAddress((void**)&hsh, g_hsh); cudaGetSymbolAddress((void**)&hsl, g_hsl);
    cudaGetSymbolAddress((void**)&qh,  g_qh);  cudaGetSymbolAddress((void**)&ql,  g_ql);
    cudaGetSymbolAddress((void**)&kh,  g_kh);  cudaGetSymbolAddress((void**)&kl,  g_kl);
    cudaGetSymbolAddress((void**)&vth, g_vth); cudaGetSymbolAddress((void**)&vtl, g_vtl);
    cudaGetSymbolAddress((void**)&ath, g_ath); cudaGetSymbolAddress((void**)&atl, g_atl);
    cudaGetSymbolAddress((void**)&wallh, g_wallh); cudaGetSymbolAddress((void**)&walll, g_walll);
    cudaGetSymbolAddress((void**)&woh, g_woh); cudaGetSymbolAddress((void**)&wol, g_wol);

    cudaFuncSetAttribute(gemm_bf16s,
        cudaFuncAttributeMaxDynamicSharedMemorySize, GEMM_SMEM);
    cudaFuncSetAttribute(gemm_bf16s_n64,
        cudaFuncAttributeMaxDynamicSharedMemorySize, N64_SMEM);
    cudaFuncSetAttribute(attn_mma_kernel,
        cudaFuncAttributeMaxDynamicSharedMemorySize, ATT_SMEM_BYTES);

    const dim3 tb(32, 8);

    // Split hidden states; transpose+split weights (QKV fused into one launch)
    split_strided_kernel<<<(M_ * HID_ / 4 + 255) / 256, 256>>>(
        hs, hsh, hsl, M_ * HID_, 11, HID_);
    wqkv_transpose_kernel<<<dim3(NQKV_ / 32, HID_ / 32), tb>>>(
        Wq, Wk, Wv, wallh, walll);
    transpose_split_kernel<<<dim3(64, 64, 1), tb>>>(
        Wo, woh, wol, HID_, 0, QKDIM_, 0);

    // Fused QKV projection (tensor core, narrow tiles for 96% wave occupancy)
    gemm_bf16s_n64<<<dim3(NQKV_ / 64, M_ / 128), 256, N64_SMEM>>>(
        hsh, hsl, wallh, walll, qkv, M_, NQKV_, HID_);

    // Fused RoPE + split: qkv -> split Q/K directly
    {
        const int total = B_ * S_ * NH_ * (HD_ / 2) + B_ * S_ * (HD_ / 2);
        rope_split_kernel<<<(total + 255) / 256, 256>>>(qkv, pos, qh, ql, kh, kl);
    }

    // Transpose+split V per batch
    transpose_split_kernel<<<dim3(8, 64, B_), tb>>>(
        qkv + QKDIM_ + HD_, vth, vtl,
        NQKV_, (size_t)S_ * NQKV_, S_, (size_t)HD_ * S_);

    // Attention (tensor core flash)
    attn_mma_kernel<<<dim3(S_ / 64, NH_, B_), 256, ATT_SMEM_BYTES>>>(
        qh, ql, kh, kl, vth, vtl, ath, atl);

    // Output projection (tensor core, wide tiles: 512 CTAs -> 86% busy)
    gemm_bf16s<<<dim3(HID_ / 128, M_ / 128), 256, GEMM_SMEM>>>(
        ath, atl, woh, wol, out, M_, HID_, HID_);
}

// round 15
// speedup vs baseline: 1.2855x; 1.2668x over previous
#include <cuda_runtime.h>
#include <cuda_fp16.h>
#include <math.h>
#include <stdint.h>

// Problem constants
#define B_ 2
#define S_ 2048
#define HID_ 2048
#define NH_ 8
#define HD_ 256
#define M_ 4096           // B*S
#define QKDIM_ (NH_*HD_)  // 2048
#define NQKV_ 2560        // 2048 (Q) + 256 (K) + 256 (V)

typedef __half fp16;

// ---------------------------------------------------------------------------
// Scratch (device globals: allocation-free per harness rules)
// ---------------------------------------------------------------------------
__device__ float g_qkv[M_ * NQKV_];                         // fused QKV output (fp32)

__device__ fp16 g_hsh[M_ * HID_];                           // fp16 hidden states (hi only)
__device__ fp16 g_qh [M_ * QKDIM_], g_ql [M_ * QKDIM_];     // split Q (post-RoPE)
__device__ fp16 g_kh [M_ * HD_],   g_kl [M_ * HD_];         // split K
__device__ fp16 g_vth[B_ * HD_ * S_], g_vtl[B_ * HD_ * S_]; // V transposed [b][d][s]
__device__ fp16 g_ath[M_ * QKDIM_];                         // attention output (hi only)

__device__ fp16 g_wallh[NQKV_ * HID_];                      // fused [Wq;Wk;Wv]^T hi
__device__ fp16 g_walll[NQKV_ * HID_];                      // fused lo
__device__ fp16 g_woh[QKDIM_ * HID_], g_wol[QKDIM_ * HID_];

// ---------------------------------------------------------------------------
// Helpers
// ---------------------------------------------------------------------------
__device__ __forceinline__ void split1(float x, fp16& h, fp16& l) {
    h = __float2half_rn(x);
    l = __float2half_rn(x - __half2float(h));
}

__device__ __forceinline__ void mma16816(float (&d)[4], const uint32_t (&a)[4],
                                         uint32_t b0, uint32_t b1) {
    asm volatile(
        "mma.sync.aligned.m16n8k16.row.col.f32.f16.f16.f32 "
        "{%0,%1,%2,%3}, {%4,%5,%6,%7}, {%8,%9}, {%0,%1,%2,%3};\n"
        : "+f"(d[0]), "+f"(d[1]), "+f"(d[2]), "+f"(d[3])
        : "r"(a[0]), "r"(a[1]), "r"(a[2]), "r"(a[3]), "r"(b0), "r"(b1));
}

__device__ __forceinline__ void ldsm_x4(uint32_t (&r)[4], const fp16* p) {
    uint32_t a = (uint32_t)__cvta_generic_to_shared(p);
    asm volatile("ldmatrix.sync.aligned.m8n8.x4.shared.b16 {%0,%1,%2,%3}, [%4];\n"
        : "=r"(r[0]), "=r"(r[1]), "=r"(r[2]), "=r"(r[3]) : "r"(a));
}

__device__ __forceinline__ void cpasync16(fp16* s, const fp16* g) {
    uint32_t sa = (uint32_t)__cvta_generic_to_shared(s);
    asm volatile("cp.async.cg.shared.global [%0], [%1], 16;\n" :: "r"(sa), "l"(g));
}
__device__ __forceinline__ void cpcommit() {
    asm volatile("cp.async.commit_group;\n");
}
template<int N> __device__ __forceinline__ void cpwait() {
    asm volatile("cp.async.wait_group %0;\n" :: "n"(N));
}

// ---------------------------------------------------------------------------
// fp32 -> fp16 convert (hi only), for hidden states.
// ---------------------------------------------------------------------------
__global__ void cvt_kernel(const float* __restrict__ in, fp16* __restrict__ oh, int n) {
    int i = (blockIdx.x * blockDim.x + threadIdx.x) * 4;
    if (i >= n) return;
    float4 v = *(const float4*)(in + i);
    __half2 a, b;
    a.x = __float2half_rn(v.x); a.y = __float2half_rn(v.y);
    b.x = __float2half_rn(v.z); b.y = __float2half_rn(v.w);
    *(__half2*)(oh + i)     = a;
    *(__half2*)(oh + i + 2) = b;
}

// ---------------------------------------------------------------------------
// Tiled transpose + split (generic).
// ---------------------------------------------------------------------------
__global__ void transpose_split_kernel(const float* __restrict__ in,
                                       fp16* __restrict__ oh, fp16* __restrict__ ol,
                                       int ldin, size_t bsIn, int ldout, size_t bsOut) {
    __shared__ float t[32][33];
    const float* ip = in + (size_t)blockIdx.z * bsIn;
    fp16* ohp = oh + (size_t)blockIdx.z * bsOut;
    fp16* olp = ol + (size_t)blockIdx.z * bsOut;
    const int r0 = blockIdx.y * 32, c0 = blockIdx.x * 32;
    #pragma unroll
    for (int i = 0; i < 4; i++) {
        int r = threadIdx.y + i * 8;
        t[r][threadIdx.x] = ip[(size_t)(r0 + r) * ldin + c0 + threadIdx.x];
    }
    __syncthreads();
    #pragma unroll
    for (int i = 0; i < 4; i++) {
        int c = threadIdx.y + i * 8;
        float v = t[threadIdx.x][c];
        fp16 h, l; split1(v, h, l);
        size_t o = (size_t)(c0 + c) * ldout + r0 + threadIdx.x;
        ohp[o] = h; olp[o] = l;
    }
}

// ---------------------------------------------------------------------------
// Fused QKV weight transpose+split: out [2560][2048] = [Wq^T; Wk^T; Wv^T].
// ---------------------------------------------------------------------------
__global__ void wqkv_transpose_kernel(const float* __restrict__ Wq,
                                      const float* __restrict__ Wk,
                                      const float* __restrict__ Wv,
                                      fp16* __restrict__ oh, fp16* __restrict__ ol) {
    __shared__ float t[32][33];
    const int c0 = blockIdx.x * 32;   // output row block (N dim, 0..2559)
    const int r0 = blockIdx.y * 32;   // HID block
    const float* src; int ldin, cbase;
    if (c0 < QKDIM_)            { src = Wq; ldin = QKDIM_; cbase = c0; }
    else if (c0 < QKDIM_ + HD_) { src = Wk; ldin = HD_;    cbase = c0 - QKDIM_; }
    else                        { src = Wv; ldin = HD_;    cbase = c0 - QKDIM_ - HD_; }
    #pragma unroll
    for (int i = 0; i < 4; i++) {
        int r = threadIdx.y + i * 8;
        t[r][threadIdx.x] = src[(size_t)(r0 + r) * ldin + cbase + threadIdx.x];
    }
    __syncthreads();
    #pragma unroll
    for (int i = 0; i < 4; i++) {
        int c = threadIdx.y + i * 8;
        float v = t[threadIdx.x][c];
        fp16 h, l; split1(v, h, l);
        size_t o = (size_t)(c0 + c) * HID_ + r0 + threadIdx.x;
        oh[o] = h; ol[o] = l;
    }
}

// ---------------------------------------------------------------------------
// GEMM (wide): C[M,N] = A@B^T, tile 128x128, 2 CTAs/SM. O-proj.
// A fp16 hi only; B fp16 hi+lo. 2-MMA: acc += Ah*Bh + Ah*Bl.
// Planes per stage: Ah, Bh, Bl (3 x 128 x GLDA).
// ---------------------------------------------------------------------------
#define GLDA 40                    // 32 + 8 halves pad (80B row: LDSM conflict-free)
#define PLANEH (128 * GLDA)        // 5120 halves per plane
#define STAGEH (3 * PLANEH)        // Ah, Bh, Bl
#define GEMM_SMEM (2 * STAGEH * 2) // 2 stages: 61440 bytes

__global__ __launch_bounds__(256, 2) void gemm_fp16s(
    const fp16* __restrict__ Ah,
    const fp16* __restrict__ Bh, const fp16* __restrict__ Bl,
    float* __restrict__ C, int M, int N, int K)
{
    extern __shared__ fp16 sm[];
    const int tid = threadIdx.x;
    const int wid = tid >> 5, lane = tid & 31;
    const int g = lane >> 2, tg = lane & 3;
    const int m8 = lane >> 3, ri = lane & 7;
    const int wm = (wid & 3) * 32;
    const int wn = (wid >> 2) * 64;
    const int row0 = blockIdx.y * 128;
    const int col0 = blockIdx.x * 128;

    const int lr = tid >> 1;
    const int lc = (tid & 1) * 16;
    const fp16* gA  = Ah + (size_t)(row0 + lr) * K + lc;
    const fp16* gB  = Bh + (size_t)(col0 + lr) * K + lc;
    const fp16* gBl = Bl + (size_t)(col0 + lr) * K + lc;
    const int soff = lr * GLDA + lc;

    float acc[2][8][4] = {};
    const int nk = K / 32;

    auto load_stage = [&](int chunk, int st) {
        const int k0 = chunk * 32;
        fp16* s = sm + st * STAGEH + soff;
        cpasync16(s,            gA  + k0);  cpasync16(s + 8,            gA  + k0 + 8);
        cpasync16(s + PLANEH,   gB  + k0);  cpasync16(s + PLANEH + 8,   gB  + k0 + 8);
        cpasync16(s + 2*PLANEH, gBl + k0);  cpasync16(s + 2*PLANEH + 8, gBl + k0 + 8);
        cpcommit();
    };

    load_stage(0, 0);

    for (int i = 0; i < nk; i++) {
        cpwait<0>();
        __syncthreads();
        if (i + 1 < nk) load_stage(i + 1, (i + 1) & 1);

        const fp16* pAh = sm + (i & 1) * STAGEH;
        const fp16* pBh = pAh + PLANEH;
        const fp16* pBl = pAh + 2 * PLANEH;

        #pragma unroll
        for (int kk = 0; kk < 32; kk += 16) {
            uint32_t ah[2][4];
            #pragma unroll
            for (int mt = 0; mt < 2; mt++) {
                const int ao = (wm + mt * 16 + (m8 & 1) * 8 + ri) * GLDA + kk + (m8 >> 1) * 8;
                ldsm_x4(ah[mt], pAh + ao);
            }
            uint32_t bh[4][4], bl[4][4];
            #pragma unroll
            for (int p = 0; p < 4; p++) {
                const int bo = (wn + p * 16 + (m8 >> 1) * 8 + ri) * GLDA + kk + (m8 & 1) * 8;
                ldsm_x4(bh[p], pBh + bo);
                ldsm_x4(bl[p], pBl + bo);
            }
            #pragma unroll
            for (int p = 0; p < 4; p++)
                #pragma unroll
                for (int sub = 0; sub < 2; sub++) {
                    const int nt = p * 2 + sub;
                    const uint32_t h0 = bh[p][sub*2], h1 = bh[p][sub*2+1];
                    const uint32_t l0 = bl[p][sub*2], l1 = bl[p][sub*2+1];
                    #pragma unroll
                    for (int mt = 0; mt < 2; mt++) {
                        mma16816(acc[mt][nt], ah[mt], h0, h1);
                        mma16816(acc[mt][nt], ah[mt], l0, l1);
                    }
                }
        }
    }

    #pragma unroll
    for (int mt = 0; mt < 2; mt++)
        #pragma unroll
        for (int nt = 0; nt < 8; nt++) {
            const int r  = row0 + wm + mt * 16 + g;
            const int cn = col0 + wn + nt * 8 + tg * 2;
            float2 v01; v01.x = acc[mt][nt][0]; v01.y = acc[mt][nt][1];
            float2 v23; v23.x = acc[mt][nt][2]; v23.y = acc[mt][nt][3];
            *(float2*)(C + (size_t)r * N + cn)       = v01;
            *(float2*)(C + (size_t)(r + 8) * N + cn) = v23;
        }
}

// ---------------------------------------------------------------------------
// GEMM (narrow): tile 128x64, warp tile 32x32, 3 CTAs/SM. QKV projection.
// A fp16 hi only; B fp16 hi+lo. 2-MMA.
// Planes per stage: Ah 128xGLDA, Bh/Bl 64xGLDA.
// ---------------------------------------------------------------------------
#define N64_APL (128 * GLDA)             // 5120 halves (A plane)
#define N64_BPL (64 * GLDA)              // 2560 halves (B plane)
#define N64_STAGEH (N64_APL + 2 * N64_BPL)   // 10240 halves
#define N64_SMEM (2 * N64_STAGEH * 2)    // 40960 bytes

__global__ __launch_bounds__(256, 3) void gemm_fp16s_n64(
    const fp16* __restrict__ Ah,
    const fp16* __restrict__ Bh, const fp16* __restrict__ Bl,
    float* __restrict__ C, int M, int N, int K)
{
    extern __shared__ fp16 sm[];
    const int tid = threadIdx.x;
    const int wid = tid >> 5, lane = tid & 31;
    const int g = lane >> 2, tg = lane & 3;
    const int m8 = lane >> 3, ri = lane & 7;
    const int wm = (wid & 3) * 32;
    const int wn = (wid >> 2) * 32;
    const int row0 = blockIdx.y * 128;
    const int col0 = blockIdx.x * 64;

    // cp.async mapping:
    //  A: thread -> row tid>>1, 16-half chunk at (tid&1)*16 (2 cpasync16).
    //  B: thread -> row tid>>2, plane (tid>>1)&1, chunk (tid&1)*16 (2 cpasync16).
    const int alr = tid >> 1;
    const int alc = (tid & 1) * 16;
    const int blr = tid >> 2;
    const int bpl = (tid >> 1) & 1;
    const int blc = (tid & 1) * 16;
    const fp16* gA = Ah + (size_t)(row0 + alr) * K + alc;
    const fp16* gB = (bpl ? Bl : Bh) + (size_t)(col0 + blr) * K + blc;
    const int aoff = alr * GLDA + alc;
    const int boff = N64_APL + bpl * N64_BPL + blr * GLDA + blc;

    float acc[2][4][4] = {};
    const int nk = K / 32;

    auto load_stage = [&](int chunk, int st) {
        const int k0 = chunk * 32;
        fp16* s = sm + st * N64_STAGEH;
        cpasync16(s + aoff,     gA + k0);
        cpasync16(s + aoff + 8, gA + k0 + 8);
        cpasync16(s + boff,     gB + k0);
        cpasync16(s + boff + 8, gB + k0 + 8);
        cpcommit();
    };

    load_stage(0, 0);

    for (int i = 0; i < nk; i++) {
        cpwait<0>();
        __syncthreads();
        if (i + 1 < nk) load_stage(i + 1, (i + 1) & 1);

        const fp16* pAh = sm + (i & 1) * N64_STAGEH;
        const fp16* pBh = pAh + N64_APL;
        const fp16* pBl = pBh + N64_BPL;

        #pragma unroll
        for (int kk = 0; kk < 32; kk += 16) {
            uint32_t ah[2][4];
            #pragma unroll
            for (int mt = 0; mt < 2; mt++) {
                const int ao = (wm + mt * 16 + (m8 & 1) * 8 + ri) * GLDA + kk + (m8 >> 1) * 8;
                ldsm_x4(ah[mt], pAh + ao);
            }
            #pragma unroll
            for (int p = 0; p < 2; p++) {
                uint32_t bh[4], bl[4];
                const int bo = (wn + p * 16 + (m8 >> 1) * 8 + ri) * GLDA + kk + (m8 & 1) * 8;
                ldsm_x4(bh, pBh + bo);
                ldsm_x4(bl, pBl + bo);
                #pragma unroll
                for (int sub = 0; sub < 2; sub++) {
                    const int nt = p * 2 + sub;
                    const uint32_t h0 = bh[sub*2], h1 = bh[sub*2+1];
                    const uint32_t l0 = bl[sub*2], l1 = bl[sub*2+1];
                    #pragma unroll
                    for (int mt = 0; mt < 2; mt++) {
                        mma16816(acc[mt][nt], ah[mt], h0, h1);
                        mma16816(acc[mt][nt], ah[mt], l0, l1);
                    }
                }
            }
        }
    }

    #pragma unroll
    for (int mt = 0; mt < 2; mt++)
        #pragma unroll
        for (int nt = 0; nt < 4; nt++) {
            const int r  = row0 + wm + mt * 16 + g;
            const int cn = col0 + wn + nt * 8 + tg * 2;
            float2 v01; v01.x = acc[mt][nt][0]; v01.y = acc[mt][nt][1];
            float2 v23; v23.x = acc[mt][nt][2]; v23.y = acc[mt][nt][3];
            *(float2*)(C + (size_t)r * N + cn)       = v01;
            *(float2*)(C + (size_t)(r + 8) * N + cn) = v23;
        }
}

// ---------------------------------------------------------------------------
// Fused RoPE + split: reads fp32 pairs from qkv, rotates, writes split fp16
// directly into qh/ql (Q) and kh/kl (K).
// ---------------------------------------------------------------------------
__global__ void rope_split_kernel(const float* __restrict__ qkv,
                                  const int* __restrict__ pos,
                                  fp16* __restrict__ qh, fp16* __restrict__ ql,
                                  fp16* __restrict__ kh, fp16* __restrict__ kl)
{
    const int QP = B_ * S_ * NH_ * (HD_ / 2);
    const int KP = B_ * S_ * (HD_ / 2);
    int idx = blockIdx.x * blockDim.x + threadIdx.x;
    if (idx >= QP + KP) return;
    const float L2B = 13.28771237954945f;  // log2(10000)

    int i, bs;
    const float* base;
    fp16 *oh, *ol;
    size_t oo;
    if (idx < QP) {
        i  = idx & 127;
        const int h = (idx >> 7) & 7;
        bs = idx >> 10;
        base = qkv + (size_t)bs * NQKV_ + h * HD_;
        oo = (size_t)bs * QKDIM_ + h * HD_;
        oh = qh; ol = ql;
    } else {
        const int j = idx - QP;
        i  = j & 127;
        bs = j >> 7;
        base = qkv + (size_t)bs * NQKV_ + QKDIM_;
        oo = (size_t)bs * HD_;
        oh = kh; ol = kl;
    }
    const float inv = exp2f(-(float)(2 * i) * (L2B / 256.f));
    const float ang = (float)pos[bs] * inv;
    float sn, cs; sincosf(ang, &sn, &cs);
    const float x1 = base[i], x2 = base[i + 128];
    const float o1 = x1 * cs - x2 * sn;
    const float o2 = x2 * cs + x1 * sn;
    fp16 h1, l1, h2, l2;
    split1(o1, h1, l1); split1(o2, h2, l2);
    oh[oo + i]       = h1;  ol[oo + i]       = l1;
    oh[oo + i + 128] = h2;  ol[oo + i + 128] = l2;
}

// ---------------------------------------------------------------------------
// Flash attention, fp16-split MMAs + ldmatrix (3-term, unchanged structure).
// Epilogue writes only fp16 hi (O-proj uses 2-term).
// ---------------------------------------------------------------------------
#define AQ_LD 264
#define AP_LD 72
#define AQ_HALVES (64 * AQ_LD)
#define AV_HALVES (256 * AP_LD)
#define APB_HALVES (64 * AP_LD)

#define ATT_SMEM_BYTES ((4*AQ_HALVES + 2*AV_HALVES + 2*APB_HALVES) * 2 + (3*64 + 256) * 4)

__global__ __launch_bounds__(256, 1) void attn_mma_kernel(
    const fp16* __restrict__ qh, const fp16* __restrict__ ql,
    const fp16* __restrict__ kh, const fp16* __restrict__ kl,
    const fp16* __restrict__ vth, const fp16* __restrict__ vtl,
    fp16* __restrict__ ath)
{
    extern __shared__ char smraw[];
    fp16* Qh = (fp16*)smraw;
    fp16* Ql = Qh + AQ_HALVES;
    fp16* Kh = Ql + AQ_HALVES;
    fp16* Kl = Kh + AQ_HALVES;
    fp16* Vh = Kl + AQ_HALVES;
    fp16* Vl = Vh + AV_HALVES;
    fp16* Ph = Vl + AV_HALVES;
    fp16* Pl = Ph + APB_HALVES;
    float* Ms = (float*)(Pl + APB_HALVES);
    float* Ls = Ms + 64;
    float* Cr = Ls + 64;
    float* Mx = Cr + 64;
    float* Sx = Mx + 128;

    const int qt = (int)gridDim.x - 1 - (int)blockIdx.x;
    const int h  = blockIdx.y;
    const int b  = blockIdx.z;
    const int tid = threadIdx.x;
    const int wid = tid >> 5, lane = tid & 31;
    const int g = lane >> 2, tg = lane & 3;
    const int m8 = lane >> 3, ri = lane & 7;
    const int wm  = (wid & 3) * 16;
    const int wn2 = (wid >> 2) * 32;
    const int wd  = (wid >> 2) * 128;
    const int half = wid >> 2;
    const int barid = (wid & 3) + 1;
    const int q0 = qt * 64;
    const float scale = 0.0625f;

    {
        #pragma unroll
        for (int j = 0; j < 8; j++) {
            const int c = tid + 256 * j;
            const int r = c >> 5, cc = (c & 31) * 8;
            const size_t go = (size_t)(b * S_ + q0 + r) * QKDIM_ + h * HD_ + cc;
            cpasync16(Qh + r * AQ_LD + cc, qh + go);
            cpasync16(Ql + r * AQ_LD + cc, ql + go);
        }
        cpcommit();
        #pragma unroll
        for (int j = 0; j < 8; j++) {
            const int c = tid + 256 * j;
            const int r = c >> 5, cc = (c & 31) * 8;
            const size_t go = (size_t)(b * S_ + r) * HD_ + cc;
            cpasync16(Kh + r * AQ_LD + cc, kh + go);
            cpasync16(Kl + r * AQ_LD + cc, kl + go);
        }
        cpcommit();
    }
    if (tid < 64) { Ms[tid] = -INFINITY; Ls[tid] = 0.f; Cr[tid] = 0.f; }

    float oc[16][4] = {};

    for (int kt = 0; kt <= qt; ++kt) {
        const int k0 = kt * 64;
        cpwait<0>();
        __syncthreads();   // B

        #pragma unroll
        for (int j = 0; j < 8; j++) {
            const int c = tid + 256 * j;
            const int r = c >> 3, cc = (c & 7) * 8;
            const size_t go = (size_t)b * HD_ * S_ + (size_t)r * S_ + k0 + cc;
            cpasync16(Vh + r * AP_LD + cc, vth + go);
            cpasync16(Vl + r * AP_LD + cc, vtl + go);
        }
        cpcommit();

        float sc[4][4] = {};
        #pragma unroll
        for (int kk = 0; kk < 256; kk += 16) {
            uint32_t ah[4], al[4];
            {
                const int ao = (wm + (m8 & 1) * 8 + ri) * AQ_LD + kk + (m8 >> 1) * 8;
                ldsm_x4(ah, Qh + ao);
                ldsm_x4(al, Ql + ao);
            }
            uint32_t bh[2][4], bl[2][4];
            #pragma unroll
            for (int p = 0; p < 2; p++) {
                const int bo = (wn2 + p * 16 + (m8 >> 1) * 8 + ri) * AQ_LD + kk + (m8 & 1) * 8;
                ldsm_x4(bh[p], Kh + bo);
                ldsm_x4(bl[p], Kl + bo);
            }
            #pragma unroll
            for (int p = 0; p < 2; p++)
                #pragma unroll
                for (int sub = 0; sub < 2; sub++) {
                    const int nt = p * 2 + sub;
                    mma16816(sc[nt], ah, bh[p][sub*2], bh[p][sub*2+1]);
                    mma16816(sc[nt], ah, bl[p][sub*2], bl[p][sub*2+1]);
                    mma16816(sc[nt], al, bh[p][sub*2], bh[p][sub*2+1]);
                }
        }

        const int r0g = q0 + wm + g;
        const int r1g = r0g + 8;
        #pragma unroll
        for (int nt = 0; nt < 4; nt++) {
            const int col = k0 + wn2 + nt * 8 + tg * 2;
            sc[nt][0] = (col     > r0g) ? -1e30f : sc[nt][0] * scale;
            sc[nt][1] = (col + 1 > r0g) ? -1e30f : sc[nt][1] * scale;
            sc[nt][2] = (col     > r1g) ? -1e30f : sc[nt][2] * scale;
            sc[nt][3] = (col + 1 > r1g) ? -1e30f : sc[nt][3] * scale;
        }

        const int lr0 = wm + g, lr1 = lr0 + 8;
        float mx0 = -INFINITY, mx1 = -INFINITY;
        #pragma unroll
        for (int nt = 0; nt < 4; nt++) {
            mx0 = fmaxf(mx0, fmaxf(sc[nt][0], sc[nt][1]));
            mx1 = fmaxf(mx1, fmaxf(sc[nt][2], sc[nt][3]));
        }
        mx0 = fmaxf(mx0, __shfl_xor_sync(0xffffffffu, mx0, 1));
        mx0 = fmaxf(mx0, __shfl_xor_sync(0xffffffffu, mx0, 2));
        mx1 = fmaxf(mx1, __shfl_xor_sync(0xffffffffu, mx1, 1));
        mx1 = fmaxf(mx1, __shfl_xor_sync(0xffffffffu, mx1, 2));
        if (tg == 0) { Mx[half * 64 + lr0] = mx0; Mx[half * 64 + lr1] = mx1; }
        asm volatile("bar.sync %0, 64;" :: "r"(barid) : "memory");   // D

        const float mo0 = Ms[lr0], mo1 = Ms[lr1];
        const float mn0 = fmaxf(fmaxf(Mx[lr0], Mx[64 + lr0]), mo0);
        const float mn1 = fmaxf(fmaxf(Mx[lr1], Mx[64 + lr1]), mo1);
        float sum0 = 0.f, sum1 = 0.f;
        #pragma unroll
        for (int nt = 0; nt < 4; nt++) {
            const int colL = wn2 + nt * 8 + tg * 2;
            const float p0 = __expf(sc[nt][0] - mn0);
            const float p1 = __expf(sc[nt][1] - mn0);
            const float p2 = __expf(sc[nt][2] - mn1);
            const float p3 = __expf(sc[nt][3] - mn1);
            sum0 += p0 + p1; sum1 += p2 + p3;
            fp16 hb0,lb0,hb1,lb1,hb2,lb2,hb3,lb3;
            split1(p0,hb0,lb0); split1(p1,hb1,lb1);
            split1(p2,hb2,lb2); split1(p3,hb3,lb3);
            __half2 t;
            t.x=hb0; t.y=hb1; *(__half2*)(Ph + lr0 * AP_LD + colL) = t;
            t.x=lb0; t.y=lb1; *(__half2*)(Pl + lr0 * AP_LD + colL) = t;
            t.x=hb2; t.y=hb3; *(__half2*)(Ph + lr1 * AP_LD + colL) = t;
            t.x=lb2; t.y=lb3; *(__half2*)(Pl + lr1 * AP_LD + colL) = t;
        }
        sum0 += __shfl_xor_sync(0xffffffffu, sum0, 1);
        sum0 += __shfl_xor_sync(0xffffffffu, sum0, 2);
        sum1 += __shfl_xor_sync(0xffffffffu, sum1, 1);
        sum1 += __shfl_xor_sync(0xffffffffu, sum1, 2);
        if (tg == 0) { Sx[half * 64 + lr0] = sum0; Sx[half * 64 + lr1] = sum1; }
        asm volatile("bar.sync %0, 64;" :: "r"(barid) : "memory");   // E

        if (wid < 4 && lane < 16) {
            const int row = wm + lane;
            const float mo = Ms[row];
            const float mn = fmaxf(fmaxf(Mx[row], Mx[64 + row]), mo);
            const float corr = (mo == -INFINITY) ? 0.f : __expf(mo - mn);
            Ls[row] = Ls[row] * corr + Sx[row] + Sx[64 + row];
            Ms[row] = mn;
            Cr[row] = corr;
        }
        cpwait<0>();
        __syncthreads();   // F

        if (kt < qt) {
            const int kn = k0 + 64;
            #pragma unroll
            for (int j = 0; j < 8; j++) {
                const int c = tid + 256 * j;
                const int r = c >> 5, cc = (c & 31) * 8;
                const size_t go = (size_t)(b * S_ + kn + r) * HD_ + cc;
                cpasync16(Kh + r * AQ_LD + cc, kh + go);
                cpasync16(Kl + r * AQ_LD + cc, kl + go);
            }
            cpcommit();
        }

        const float cr0 = Cr[wm + g], cr1 = Cr[wm + g + 8];
        #pragma unroll
        for (int nt = 0; nt < 16; nt++) {
            oc[nt][0] *= cr0; oc[nt][1] *= cr0;
            oc[nt][2] *= cr1; oc[nt][3] *= cr1;
        }
        #pragma unroll
        for (int kk = 0; kk < 64; kk += 16) {
            uint32_t pa[4], pl_[4];
            {
                const int ao = (wm + (m8 & 1) * 8 + ri) * AP_LD + kk + (m8 >> 1) * 8;
                ldsm_x4(pa,  Ph + ao);
                ldsm_x4(pl_, Pl + ao);
            }
            #pragma unroll
            for (int p = 0; p < 8; p++) {
                uint32_t bh[4], bl[4];
                const int bo = (wd + p * 16 + (m8 >> 1) * 8 + ri) * AP_LD + kk + (m8 & 1) * 8;
                ldsm_x4(bh, Vh + bo);
                ldsm_x4(bl, Vl + bo);
                #pragma unroll
                for (int sub = 0; sub < 2; sub++) {
                    const int nt = p * 2 + sub;
                    mma16816(oc[nt], pa,  bh[sub*2], bh[sub*2+1]);
                    mma16816(oc[nt], pa,  bl[sub*2], bl[sub*2+1]);
                    mma16816(oc[nt], pl_, bh[sub*2], bh[sub*2+1]);
                }
            }
        }
    }

    const float inv0 = 1.f / Ls[wm + g];
    const float inv1 = 1.f / Ls[wm + g + 8];
    #pragma unroll
    for (int nt = 0; nt < 16; nt++) {
        const int d = wd + nt * 8 + tg * 2;
        const size_t base0 = (size_t)(b * S_ + q0 + wm + g) * QKDIM_ + h * HD_ + d;
        const size_t base1 = base0 + 8 * QKDIM_;
        __half2 t;
        t.x = __float2half_rn(oc[nt][0] * inv0);
        t.y = __float2half_rn(oc[nt][1] * inv0);
        *(__half2*)(ath + base0) = t;
        t.x = __float2half_rn(oc[nt][2] * inv1);
        t.y = __float2half_rn(oc[nt][3] * inv1);
        *(__half2*)(ath + base1) = t;
    }
}

// ---------------------------------------------------------------------------
// Launch
// Inputs: 0=hidden_states 1=attention_mask(unused) 2=position_ids
//         3=Wq 4=Wk 5=Wv 6=Wo
// ---------------------------------------------------------------------------
extern "C" void kernel_launch(void* const* d_in, const int* in_sizes, int n_in,
                              void* d_out, int out_size) {
    (void)in_sizes; (void)n_in; (void)out_size;
    const float* hs  = (const float*)d_in[0];
    const int*   pos = (const int*)  d_in[2];
    const float* Wq  = (const float*)d_in[3];
    const float* Wk  = (const float*)d_in[4];
    const float* Wv  = (const float*)d_in[5];
    const float* Wo  = (const float*)d_in[6];
    float* out = (float*)d_out;

    float *qkv;
    fp16 *hsh,*qh,*ql,*kh,*kl,*vth,*vtl,*ath;
    fp16 *wallh,*walll,*woh,*wol;
    cudaGetSymbolAddress((void**)&qkv, g_qkv);
    cudaGetSymbolAddress((void**)&hsh, g_hsh);
    cudaGetSymbolAddress((void**)&qh,  g_qh);  cudaGetSymbolAddress((void**)&ql,  g_ql);
    cudaGetSymbolAddress((void**)&kh,  g_kh);  cudaGetSymbolAddress((void**)&kl,  g_kl);
    cudaGetSymbolAddress((void**)&vth, g_vth); cudaGetSymbolAddress((void**)&vtl, g_vtl);
    cudaGetSymbolAddress((void**)&ath, g_ath);
    cudaGetSymbolAddress((void**)&wallh, g_wallh); cudaGetSymbolAddress((void**)&walll, g_walll);
    cudaGetSymbolAddress((void**)&woh, g_woh); cudaGetSymbolAddress((void**)&wol, g_wol);

    cudaFuncSetAttribute(gemm_fp16s,
        cudaFuncAttributeMaxDynamicSharedMemorySize, GEMM_SMEM);
    cudaFuncSetAttribute(gemm_fp16s_n64,
        cudaFuncAttributeMaxDynamicSharedMemorySize, N64_SMEM);
    cudaFuncSetAttribute(attn_mma_kernel,
        cudaFuncAttributeMaxDynamicSharedMemorySize, ATT_SMEM_BYTES);

    const dim3 tb(32, 8);

    // Convert hidden states to fp16 (hi only); transpose+split weights
    cvt_kernel<<<(M_ * HID_ / 4 + 255) / 256, 256>>>(hs, hsh, M_ * HID_);
    wqkv_transpose_kernel<<<dim3(NQKV_ / 32, HID_ / 32), tb>>>(
        Wq, Wk, Wv, wallh, walll);
    transpose_split_kernel<<<dim3(64, 64, 1), tb>>>(
        Wo, woh, wol, HID_, 0, QKDIM_, 0);

    // Fused QKV projection (2-MMA fp16, narrow tiles)
    gemm_fp16s_n64<<<dim3(NQKV_ / 64, M_ / 128), 256, N64_SMEM>>>(
        hsh, wallh, walll, qkv, M_, NQKV_, HID_);

    // Fused RoPE + split: qkv -> split Q/K directly
    {
        const int total = B_ * S_ * NH_ * (HD_ / 2) + B_ * S_ * (HD_ / 2);
        rope_split_kernel<<<(total + 255) / 256, 256>>>(qkv, pos, qh, ql, kh, kl);
    }

    // Transpose+split V per batch
    transpose_split_kernel<<<dim3(8, 64, B_), tb>>>(
        qkv + QKDIM_ + HD_, vth, vtl,
        NQKV_, (size_t)S_ * NQKV_, S_, (size_t)HD_ * S_);

    // Attention (fp16 3-term flash)
    attn_mma_kernel<<<dim3(S_ / 64, NH_, B_), 256, ATT_SMEM_BYTES>>>(
        qh, ql, kh, kl, vth, vtl, ath);

    // Output projection (2-MMA fp16, wide tiles)
    gemm_fp16s<<<dim3(HID_ / 128, M_ / 128), 256, GEMM_SMEM>>>(
        ath, woh, wol, out, M_, HID_, HID_);
}

// round 17
// speedup vs baseline: 1.3700x; 1.0658x over previous
#include <cuda_runtime.h>
#include <cuda_fp16.h>
#include <math.h>
#include <stdint.h>

// Problem constants
#define B_ 2
#define S_ 2048
#define HID_ 2048
#define NH_ 8
#define HD_ 256
#define M_ 4096           // B*S
#define QKDIM_ (NH_*HD_)  // 2048
#define NQKV_ 2560        // 2048 (Q) + 256 (K) + 256 (V)

typedef __half fp16;

// ---------------------------------------------------------------------------
// Scratch (device globals: allocation-free per harness rules)
// ---------------------------------------------------------------------------
__device__ float g_qkv[M_ * NQKV_];                         // fused QKV output (fp32)

__device__ fp16 g_hsh[M_ * HID_];                           // fp16 hidden states (hi only)
__device__ fp16 g_qh [M_ * QKDIM_];                         // Q post-RoPE (hi only)
__device__ fp16 g_kh [M_ * HD_],   g_kl [M_ * HD_];         // split K
__device__ fp16 g_vth[B_ * HD_ * S_], g_vtl[B_ * HD_ * S_]; // V transposed [b][d][s]
__device__ fp16 g_ath[M_ * QKDIM_];                         // attention output (hi only)

__device__ fp16 g_wallh[NQKV_ * HID_];                      // fused [Wq;Wk;Wv]^T hi
__device__ fp16 g_walll[NQKV_ * HID_];                      // fused lo
__device__ fp16 g_woh[QKDIM_ * HID_], g_wol[QKDIM_ * HID_];

// ---------------------------------------------------------------------------
// Helpers
// ---------------------------------------------------------------------------
__device__ __forceinline__ void split1(float x, fp16& h, fp16& l) {
    h = __float2half_rn(x);
    l = __float2half_rn(x - __half2float(h));
}

__device__ __forceinline__ void mma16816(float (&d)[4], const uint32_t (&a)[4],
                                         uint32_t b0, uint32_t b1) {
    asm volatile(
        "mma.sync.aligned.m16n8k16.row.col.f32.f16.f16.f32 "
        "{%0,%1,%2,%3}, {%4,%5,%6,%7}, {%8,%9}, {%0,%1,%2,%3};\n"
        : "+f"(d[0]), "+f"(d[1]), "+f"(d[2]), "+f"(d[3])
        : "r"(a[0]), "r"(a[1]), "r"(a[2]), "r"(a[3]), "r"(b0), "r"(b1));
}

__device__ __forceinline__ void ldsm_x4(uint32_t (&r)[4], const fp16* p) {
    uint32_t a = (uint32_t)__cvta_generic_to_shared(p);
    asm volatile("ldmatrix.sync.aligned.m8n8.x4.shared.b16 {%0,%1,%2,%3}, [%4];\n"
        : "=r"(r[0]), "=r"(r[1]), "=r"(r[2]), "=r"(r[3]) : "r"(a));
}

__device__ __forceinline__ void cpasync16(fp16* s, const fp16* g) {
    uint32_t sa = (uint32_t)__cvta_generic_to_shared(s);
    asm volatile("cp.async.cg.shared.global [%0], [%1], 16;\n" :: "r"(sa), "l"(g));
}
__device__ __forceinline__ void cpcommit() {
    asm volatile("cp.async.commit_group;\n");
}
template<int N> __device__ __forceinline__ void cpwait() {
    asm volatile("cp.async.wait_group %0;\n" :: "n"(N));
}

// ---------------------------------------------------------------------------
// fp32 -> fp16 convert (hi only), for hidden states.
// ---------------------------------------------------------------------------
__global__ void cvt_kernel(const float* __restrict__ in, fp16* __restrict__ oh, int n) {
    int i = (blockIdx.x * blockDim.x + threadIdx.x) * 4;
    if (i >= n) return;
    float4 v = *(const float4*)(in + i);
    __half2 a, b;
    a.x = __float2half_rn(v.x); a.y = __float2half_rn(v.y);
    b.x = __float2half_rn(v.z); b.y = __float2half_rn(v.w);
    *(__half2*)(oh + i)     = a;
    *(__half2*)(oh + i + 2) = b;
}

// ---------------------------------------------------------------------------
// Tiled transpose + split (generic).
// ---------------------------------------------------------------------------
__global__ void transpose_split_kernel(const float* __restrict__ in,
                                       fp16* __restrict__ oh, fp16* __restrict__ ol,
                                       int ldin, size_t bsIn, int ldout, size_t bsOut) {
    __shared__ float t[32][33];
    const float* ip = in + (size_t)blockIdx.z * bsIn;
    fp16* ohp = oh + (size_t)blockIdx.z * bsOut;
    fp16* olp = ol + (size_t)blockIdx.z * bsOut;
    const int r0 = blockIdx.y * 32, c0 = blockIdx.x * 32;
    #pragma unroll
    for (int i = 0; i < 4; i++) {
        int r = threadIdx.y + i * 8;
        t[r][threadIdx.x] = ip[(size_t)(r0 + r) * ldin + c0 + threadIdx.x];
    }
    __syncthreads();
    #pragma unroll
    for (int i = 0; i < 4; i++) {
        int c = threadIdx.y + i * 8;
        float v = t[threadIdx.x][c];
        fp16 h, l; split1(v, h, l);
        size_t o = (size_t)(c0 + c) * ldout + r0 + threadIdx.x;
        ohp[o] = h; olp[o] = l;
    }
}

// ---------------------------------------------------------------------------
// Fused QKV weight transpose+split: out [2560][2048] = [Wq^T; Wk^T; Wv^T].
// ---------------------------------------------------------------------------
__global__ void wqkv_transpose_kernel(const float* __restrict__ Wq,
                                      const float* __restrict__ Wk,
                                      const float* __restrict__ Wv,
                                      fp16* __restrict__ oh, fp16* __restrict__ ol) {
    __shared__ float t[32][33];
    const int c0 = blockIdx.x * 32;   // output row block (N dim, 0..2559)
    const int r0 = blockIdx.y * 32;   // HID block
    const float* src; int ldin, cbase;
    if (c0 < QKDIM_)            { src = Wq; ldin = QKDIM_; cbase = c0; }
    else if (c0 < QKDIM_ + HD_) { src = Wk; ldin = HD_;    cbase = c0 - QKDIM_; }
    else                        { src = Wv; ldin = HD_;    cbase = c0 - QKDIM_ - HD_; }
    #pragma unroll
    for (int i = 0; i < 4; i++) {
        int r = threadIdx.y + i * 8;
        t[r][threadIdx.x] = src[(size_t)(r0 + r) * ldin + cbase + threadIdx.x];
    }
    __syncthreads();
    #pragma unroll
    for (int i = 0; i < 4; i++) {
        int c = threadIdx.y + i * 8;
        float v = t[threadIdx.x][c];
        fp16 h, l; split1(v, h, l);
        size_t o = (size_t)(c0 + c) * HID_ + r0 + threadIdx.x;
        oh[o] = h; ol[o] = l;
    }
}

// ---------------------------------------------------------------------------
// GEMM (wide): C[M,N] = A@B^T, tile 128x128, 2 CTAs/SM. O-proj.
// A fp16 hi only; B fp16 hi+lo. 2-MMA: acc += Ah*Bh + Ah*Bl.
// ---------------------------------------------------------------------------
#define GLDA 40                    // 32 + 8 halves pad (80B row: LDSM conflict-free)
#define PLANEH (128 * GLDA)        // 5120 halves per plane
#define STAGEH (3 * PLANEH)        // Ah, Bh, Bl
#define GEMM_SMEM (2 * STAGEH * 2) // 2 stages: 61440 bytes

__global__ __launch_bounds__(256, 2) void gemm_fp16s(
    const fp16* __restrict__ Ah,
    const fp16* __restrict__ Bh, const fp16* __restrict__ Bl,
    float* __restrict__ C, int M, int N, int K)
{
    extern __shared__ fp16 sm[];
    const int tid = threadIdx.x;
    const int wid = tid >> 5, lane = tid & 31;
    const int g = lane >> 2, tg = lane & 3;
    const int m8 = lane >> 3, ri = lane & 7;
    const int wm = (wid & 3) * 32;
    const int wn = (wid >> 2) * 64;
    const int row0 = blockIdx.y * 128;
    const int col0 = blockIdx.x * 128;

    const int lr = tid >> 1;
    const int lc = (tid & 1) * 16;
    const fp16* gA  = Ah + (size_t)(row0 + lr) * K + lc;
    const fp16* gB  = Bh + (size_t)(col0 + lr) * K + lc;
    const fp16* gBl = Bl + (size_t)(col0 + lr) * K + lc;
    const int soff = lr * GLDA + lc;

    float acc[2][8][4] = {};
    const int nk = K / 32;

    auto load_stage = [&](int chunk, int st) {
        const int k0 = chunk * 32;
        fp16* s = sm + st * STAGEH + soff;
        cpasync16(s,            gA  + k0);  cpasync16(s + 8,            gA  + k0 + 8);
        cpasync16(s + PLANEH,   gB  + k0);  cpasync16(s + PLANEH + 8,   gB  + k0 + 8);
        cpasync16(s + 2*PLANEH, gBl + k0);  cpasync16(s + 2*PLANEH + 8, gBl + k0 + 8);
        cpcommit();
    };

    load_stage(0, 0);

    for (int i = 0; i < nk; i++) {
        cpwait<0>();
        __syncthreads();
        if (i + 1 < nk) load_stage(i + 1, (i + 1) & 1);

        const fp16* pAh = sm + (i & 1) * STAGEH;
        const fp16* pBh = pAh + PLANEH;
        const fp16* pBl = pAh + 2 * PLANEH;

        #pragma unroll
        for (int kk = 0; kk < 32; kk += 16) {
            uint32_t ah[2][4];
            #pragma unroll
            for (int mt = 0; mt < 2; mt++) {
                const int ao = (wm + mt * 16 + (m8 & 1) * 8 + ri) * GLDA + kk + (m8 >> 1) * 8;
                ldsm_x4(ah[mt], pAh + ao);
            }
            uint32_t bh[4][4], bl[4][4];
            #pragma unroll
            for (int p = 0; p < 4; p++) {
                const int bo = (wn + p * 16 + (m8 >> 1) * 8 + ri) * GLDA + kk + (m8 & 1) * 8;
                ldsm_x4(bh[p], pBh + bo);
                ldsm_x4(bl[p], pBl + bo);
            }
            #pragma unroll
            for (int p = 0; p < 4; p++)
                #pragma unroll
                for (int sub = 0; sub < 2; sub++) {
                    const int nt = p * 2 + sub;
                    const uint32_t h0 = bh[p][sub*2], h1 = bh[p][sub*2+1];
                    const uint32_t l0 = bl[p][sub*2], l1 = bl[p][sub*2+1];
                    #pragma unroll
                    for (int mt = 0; mt < 2; mt++) {
                        mma16816(acc[mt][nt], ah[mt], h0, h1);
                        mma16816(acc[mt][nt], ah[mt], l0, l1);
                    }
                }
        }
    }

    #pragma unroll
    for (int mt = 0; mt < 2; mt++)
        #pragma unroll
        for (int nt = 0; nt < 8; nt++) {
            const int r  = row0 + wm + mt * 16 + g;
            const int cn = col0 + wn + nt * 8 + tg * 2;
            float2 v01; v01.x = acc[mt][nt][0]; v01.y = acc[mt][nt][1];
            float2 v23; v23.x = acc[mt][nt][2]; v23.y = acc[mt][nt][3];
            *(float2*)(C + (size_t)r * N + cn)       = v01;
            *(float2*)(C + (size_t)(r + 8) * N + cn) = v23;
        }
}

// ---------------------------------------------------------------------------
// GEMM (narrow): tile 128x64, warp tile 32x32, 3 CTAs/SM. QKV projection.
// ---------------------------------------------------------------------------
#define N64_APL (128 * GLDA)             // 5120 halves (A plane)
#define N64_BPL (64 * GLDA)              // 2560 halves (B plane)
#define N64_STAGEH (N64_APL + 2 * N64_BPL)   // 10240 halves
#define N64_SMEM (2 * N64_STAGEH * 2)    // 40960 bytes

__global__ __launch_bounds__(256, 3) void gemm_fp16s_n64(
    const fp16* __restrict__ Ah,
    const fp16* __restrict__ Bh, const fp16* __restrict__ Bl,
    float* __restrict__ C, int M, int N, int K)
{
    extern __shared__ fp16 sm[];
    const int tid = threadIdx.x;
    const int wid = tid >> 5, lane = tid & 31;
    const int g = lane >> 2, tg = lane & 3;
    const int m8 = lane >> 3, ri = lane & 7;
    const int wm = (wid & 3) * 32;
    const int wn = (wid >> 2) * 32;
    const int row0 = blockIdx.y * 128;
    const int col0 = blockIdx.x * 64;

    const int alr = tid >> 1;
    const int alc = (tid & 1) * 16;
    const int blr = tid >> 2;
    const int bpl = (tid >> 1) & 1;
    const int blc = (tid & 1) * 16;
    const fp16* gA = Ah + (size_t)(row0 + alr) * K + alc;
    const fp16* gB = (bpl ? Bl : Bh) + (size_t)(col0 + blr) * K + blc;
    const int aoff = alr * GLDA + alc;
    const int boff = N64_APL + bpl * N64_BPL + blr * GLDA + blc;

    float acc[2][4][4] = {};
    const int nk = K / 32;

    auto load_stage = [&](int chunk, int st) {
        const int k0 = chunk * 32;
        fp16* s = sm + st * N64_STAGEH;
        cpasync16(s + aoff,     gA + k0);
        cpasync16(s + aoff + 8, gA + k0 + 8);
        cpasync16(s + boff,     gB + k0);
        cpasync16(s + boff + 8, gB + k0 + 8);
        cpcommit();
    };

    load_stage(0, 0);

    for (int i = 0; i < nk; i++) {
        cpwait<0>();
        __syncthreads();
        if (i + 1 < nk) load_stage(i + 1, (i + 1) & 1);

        const fp16* pAh = sm + (i & 1) * N64_STAGEH;
        const fp16* pBh = pAh + N64_APL;
        const fp16* pBl = pBh + N64_BPL;

        #pragma unroll
        for (int kk = 0; kk < 32; kk += 16) {
            uint32_t ah[2][4];
            #pragma unroll
            for (int mt = 0; mt < 2; mt++) {
                const int ao = (wm + mt * 16 + (m8 & 1) * 8 + ri) * GLDA + kk + (m8 >> 1) * 8;
                ldsm_x4(ah[mt], pAh + ao);
            }
            #pragma unroll
            for (int p = 0; p < 2; p++) {
                uint32_t bh[4], bl[4];
                const int bo = (wn + p * 16 + (m8 >> 1) * 8 + ri) * GLDA + kk + (m8 & 1) * 8;
                ldsm_x4(bh, pBh + bo);
                ldsm_x4(bl, pBl + bo);
                #pragma unroll
                for (int sub = 0; sub < 2; sub++) {
                    const int nt = p * 2 + sub;
                    const uint32_t h0 = bh[sub*2], h1 = bh[sub*2+1];
                    const uint32_t l0 = bl[sub*2], l1 = bl[sub*2+1];
                    #pragma unroll
                    for (int mt = 0; mt < 2; mt++) {
                        mma16816(acc[mt][nt], ah[mt], h0, h1);
                        mma16816(acc[mt][nt], ah[mt], l0, l1);
                    }
                }
            }
        }
    }

    #pragma unroll
    for (int mt = 0; mt < 2; mt++)
        #pragma unroll
        for (int nt = 0; nt < 4; nt++) {
            const int r  = row0 + wm + mt * 16 + g;
            const int cn = col0 + wn + nt * 8 + tg * 2;
            float2 v01; v01.x = acc[mt][nt][0]; v01.y = acc[mt][nt][1];
            float2 v23; v23.x = acc[mt][nt][2]; v23.y = acc[mt][nt][3];
            *(float2*)(C + (size_t)r * N + cn)       = v01;
            *(float2*)(C + (size_t)(r + 8) * N + cn) = v23;
        }
}

// ---------------------------------------------------------------------------
// Fused RoPE + split: Q -> hi only; K -> hi+lo.
// ---------------------------------------------------------------------------
__global__ void rope_split_kernel(const float* __restrict__ qkv,
                                  const int* __restrict__ pos,
                                  fp16* __restrict__ qh,
                                  fp16* __restrict__ kh, fp16* __restrict__ kl)
{
    const int QP = B_ * S_ * NH_ * (HD_ / 2);
    const int KP = B_ * S_ * (HD_ / 2);
    int idx = blockIdx.x * blockDim.x + threadIdx.x;
    if (idx >= QP + KP) return;
    const float L2B = 13.28771237954945f;  // log2(10000)

    if (idx < QP) {
        const int i  = idx & 127;
        const int h = (idx >> 7) & 7;
        const int bs = idx >> 10;
        const float* base = qkv + (size_t)bs * NQKV_ + h * HD_;
        const size_t oo = (size_t)bs * QKDIM_ + h * HD_;
        const float inv = exp2f(-(float)(2 * i) * (L2B / 256.f));
        const float ang = (float)pos[bs] * inv;
        float sn, cs; sincosf(ang, &sn, &cs);
        const float x1 = base[i], x2 = base[i + 128];
        qh[oo + i]       = __float2half_rn(x1 * cs - x2 * sn);
        qh[oo + i + 128] = __float2half_rn(x2 * cs + x1 * sn);
    } else {
        const int j = idx - QP;
        const int i  = j & 127;
        const int bs = j >> 7;
        const float* base = qkv + (size_t)bs * NQKV_ + QKDIM_;
        const size_t oo = (size_t)bs * HD_;
        const float inv = exp2f(-(float)(2 * i) * (L2B / 256.f));
        const float ang = (float)pos[bs] * inv;
        float sn, cs; sincosf(ang, &sn, &cs);
        const float x1 = base[i], x2 = base[i + 128];
        const float o1 = x1 * cs - x2 * sn;
        const float o2 = x2 * cs + x1 * sn;
        fp16 h1, l1, h2, l2;
        split1(o1, h1, l1); split1(o2, h2, l2);
        kh[oo + i]       = h1;  kl[oo + i]       = l1;
        kh[oo + i + 128] = h2;  kl[oo + i + 128] = l2;
    }
}

// ---------------------------------------------------------------------------
// Flash attention, fp16 2-term MMAs + ldmatrix.
// S  = Qh·(Kh+Kl)   (2 MMAs per n8-tile)
// PV = Ph·(Vh+Vl)   (2 MMAs per n8-tile); P stored hi-only.
// Pipelined loads: V(kt) after sync B; K(kt+1) after sync F.
// ---------------------------------------------------------------------------
#define AQ_LD 264
#define AP_LD 72
#define AQ_HALVES (64 * AQ_LD)     // Qh / Kh / Kl planes
#define AV_HALVES (256 * AP_LD)    // Vh / Vl planes
#define APB_HALVES (64 * AP_LD)    // Ph plane

#define ATT_SMEM_BYTES ((3*AQ_HALVES + 2*AV_HALVES + APB_HALVES) * 2 + (3*64 + 256) * 4)

__global__ __launch_bounds__(256, 1) void attn_mma_kernel(
    const fp16* __restrict__ qh,
    const fp16* __restrict__ kh, const fp16* __restrict__ kl,
    const fp16* __restrict__ vth, const fp16* __restrict__ vtl,
    fp16* __restrict__ ath)
{
    extern __shared__ char smraw[];
    fp16* Qh = (fp16*)smraw;
    fp16* Kh = Qh + AQ_HALVES;
    fp16* Kl = Kh + AQ_HALVES;
    fp16* Vh = Kl + AQ_HALVES;
    fp16* Vl = Vh + AV_HALVES;
    fp16* Ph = Vl + AV_HALVES;
    float* Ms = (float*)(Ph + APB_HALVES);
    float* Ls = Ms + 64;
    float* Cr = Ls + 64;
    float* Mx = Cr + 64;
    float* Sx = Mx + 128;

    const int qt = (int)gridDim.x - 1 - (int)blockIdx.x;  // heavy tiles first
    const int h  = blockIdx.y;
    const int b  = blockIdx.z;
    const int tid = threadIdx.x;
    const int wid = tid >> 5, lane = tid & 31;
    const int g = lane >> 2, tg = lane & 3;
    const int m8 = lane >> 3, ri = lane & 7;
    const int wm  = (wid & 3) * 16;
    const int wn2 = (wid >> 2) * 32;
    const int wd  = (wid >> 2) * 128;
    const int half = wid >> 2;
    const int barid = (wid & 3) + 1;
    const int q0 = qt * 64;
    const float scale = 0.0625f;

    // prologue: Q tile (hi only) then K(0) (hi+lo)
    {
        #pragma unroll
        for (int j = 0; j < 8; j++) {
            const int c = tid + 256 * j;
            const int r = c >> 5, cc = (c & 31) * 8;
            const size_t go = (size_t)(b * S_ + q0 + r) * QKDIM_ + h * HD_ + cc;
            cpasync16(Qh + r * AQ_LD + cc, qh + go);
        }
        cpcommit();
        #pragma unroll
        for (int j = 0; j < 8; j++) {
            const int c = tid + 256 * j;
            const int r = c >> 5, cc = (c & 31) * 8;
            const size_t go = (size_t)(b * S_ + r) * HD_ + cc;
            cpasync16(Kh + r * AQ_LD + cc, kh + go);
            cpasync16(Kl + r * AQ_LD + cc, kl + go);
        }
        cpcommit();
    }
    if (tid < 64) { Ms[tid] = -INFINITY; Ls[tid] = 0.f; Cr[tid] = 0.f; }

    float oc[16][4] = {};

    for (int kt = 0; kt <= qt; ++kt) {
        const int k0 = kt * 64;
        cpwait<0>();       // K(kt) (and Q on first iter) landed
        __syncthreads();   // B: K visible; PV(kt-1) done with V and P buffers

        // Issue V(kt) load — hidden under S-MMA.
        #pragma unroll
        for (int j = 0; j < 8; j++) {
            const int c = tid + 256 * j;
            const int r = c >> 3, cc = (c & 7) * 8;
            const size_t go = (size_t)b * HD_ * S_ + (size_t)r * S_ + k0 + cc;
            cpasync16(Vh + r * AP_LD + cc, vth + go);
            cpasync16(Vl + r * AP_LD + cc, vtl + go);
        }
        cpcommit();

        // S = Qh·(Kh+Kl), 2-term
        float sc[4][4] = {};
        #pragma unroll
        for (int kk = 0; kk < 256; kk += 16) {
            uint32_t ah[4];
            {
                const int ao = (wm + (m8 & 1) * 8 + ri) * AQ_LD + kk + (m8 >> 1) * 8;
                ldsm_x4(ah, Qh + ao);
            }
            #pragma unroll
            for (int p = 0; p < 2; p++) {
                uint32_t bh[4], bl[4];
                const int bo = (wn2 + p * 16 + (m8 >> 1) * 8 + ri) * AQ_LD + kk + (m8 & 1) * 8;
                ldsm_x4(bh, Kh + bo);
                ldsm_x4(bl, Kl + bo);
                #pragma unroll
                for (int sub = 0; sub < 2; sub++) {
                    const int nt = p * 2 + sub;
                    mma16816(sc[nt], ah, bh[sub*2], bh[sub*2+1]);
                    mma16816(sc[nt], ah, bl[sub*2], bl[sub*2+1]);
                }
            }
        }

        // scale + causal mask in registers
        const int r0g = q0 + wm + g;
        const int r1g = r0g + 8;
        #pragma unroll
        for (int nt = 0; nt < 4; nt++) {
            const int col = k0 + wn2 + nt * 8 + tg * 2;
            sc[nt][0] = (col     > r0g) ? -1e30f : sc[nt][0] * scale;
            sc[nt][1] = (col + 1 > r0g) ? -1e30f : sc[nt][1] * scale;
            sc[nt][2] = (col     > r1g) ? -1e30f : sc[nt][2] * scale;
            sc[nt][3] = (col + 1 > r1g) ? -1e30f : sc[nt][3] * scale;
        }

        // In-register softmax; P stored hi-only.
        const int lr0 = wm + g, lr1 = lr0 + 8;
        float mx0 = -INFINITY, mx1 = -INFINITY;
        #pragma unroll
        for (int nt = 0; nt < 4; nt++) {
            mx0 = fmaxf(mx0, fmaxf(sc[nt][0], sc[nt][1]));
            mx1 = fmaxf(mx1, fmaxf(sc[nt][2], sc[nt][3]));
        }
        mx0 = fmaxf(mx0, __shfl_xor_sync(0xffffffffu, mx0, 1));
        mx0 = fmaxf(mx0, __shfl_xor_sync(0xffffffffu, mx0, 2));
        mx1 = fmaxf(mx1, __shfl_xor_sync(0xffffffffu, mx1, 1));
        mx1 = fmaxf(mx1, __shfl_xor_sync(0xffffffffu, mx1, 2));
        if (tg == 0) { Mx[half * 64 + lr0] = mx0; Mx[half * 64 + lr1] = mx1; }
        asm volatile("bar.sync %0, 64;" :: "r"(barid) : "memory");   // D (pair)

        const float mo0 = Ms[lr0], mo1 = Ms[lr1];
        const float mn0 = fmaxf(fmaxf(Mx[lr0], Mx[64 + lr0]), mo0);
        const float mn1 = fmaxf(fmaxf(Mx[lr1], Mx[64 + lr1]), mo1);
        float sum0 = 0.f, sum1 = 0.f;
        #pragma unroll
        for (int nt = 0; nt < 4; nt++) {
            const int colL = wn2 + nt * 8 + tg * 2;
            const float p0 = __expf(sc[nt][0] - mn0);
            const float p1 = __expf(sc[nt][1] - mn0);
            const float p2 = __expf(sc[nt][2] - mn1);
            const float p3 = __expf(sc[nt][3] - mn1);
            sum0 += p0 + p1; sum1 += p2 + p3;
            __half2 t;
            t.x = __float2half_rn(p0); t.y = __float2half_rn(p1);
            *(__half2*)(Ph + lr0 * AP_LD + colL) = t;
            t.x = __float2half_rn(p2); t.y = __float2half_rn(p3);
            *(__half2*)(Ph + lr1 * AP_LD + colL) = t;
        }
        sum0 += __shfl_xor_sync(0xffffffffu, sum0, 1);
        sum0 += __shfl_xor_sync(0xffffffffu, sum0, 2);
        sum1 += __shfl_xor_sync(0xffffffffu, sum1, 1);
        sum1 += __shfl_xor_sync(0xffffffffu, sum1, 2);
        if (tg == 0) { Sx[half * 64 + lr0] = sum0; Sx[half * 64 + lr1] = sum1; }
        asm volatile("bar.sync %0, 64;" :: "r"(barid) : "memory");   // E (pair)

        if (wid < 4 && lane < 16) {
            const int row = wm + lane;
            const float mo = Ms[row];
            const float mn = fmaxf(fmaxf(Mx[row], Mx[64 + row]), mo);
            const float corr = (mo == -INFINITY) ? 0.f : __expf(mo - mn);
            Ls[row] = Ls[row] * corr + Sx[row] + Sx[64 + row];
            Ms[row] = mn;
            Cr[row] = corr;
        }
        cpwait<0>();       // V(kt) landed
        __syncthreads();   // F: V + Ph + state visible; all warps past S-MMA

        // Issue K(kt+1) load — hidden under PV-MMA.
        if (kt < qt) {
            const int kn = k0 + 64;
            #pragma unroll
            for (int j = 0; j < 8; j++) {
                const int c = tid + 256 * j;
                const int r = c >> 5, cc = (c & 31) * 8;
                const size_t go = (size_t)(b * S_ + kn + r) * HD_ + cc;
                cpasync16(Kh + r * AQ_LD + cc, kh + go);
                cpasync16(Kl + r * AQ_LD + cc, kl + go);
            }
            cpcommit();
        }

        // Rescale accumulator, then O += Ph·(Vh+Vl), 2-term
        const float cr0 = Cr[wm + g], cr1 = Cr[wm + g + 8];
        #pragma unroll
        for (int nt = 0; nt < 16; nt++) {
            oc[nt][0] *= cr0; oc[nt][1] *= cr0;
            oc[nt][2] *= cr1; oc[nt][3] *= cr1;
        }
        #pragma unroll
        for (int kk = 0; kk < 64; kk += 16) {
            uint32_t pa[4];
            {
                const int ao = (wm + (m8 & 1) * 8 + ri) * AP_LD + kk + (m8 >> 1) * 8;
                ldsm_x4(pa, Ph + ao);
            }
            #pragma unroll
            for (int p = 0; p < 8; p++) {
                uint32_t bh[4], bl[4];
                const int bo = (wd + p * 16 + (m8 >> 1) * 8 + ri) * AP_LD + kk + (m8 & 1) * 8;
                ldsm_x4(bh, Vh + bo);
                ldsm_x4(bl, Vl + bo);
                #pragma unroll
                for (int sub = 0; sub < 2; sub++) {
                    const int nt = p * 2 + sub;
                    mma16816(oc[nt], pa, bh[sub*2], bh[sub*2+1]);
                    mma16816(oc[nt], pa, bl[sub*2], bl[sub*2+1]);
                }
            }
        }
    }

    const float inv0 = 1.f / Ls[wm + g];
    const float inv1 = 1.f / Ls[wm + g + 8];
    #pragma unroll
    for (int nt = 0; nt < 16; nt++) {
        const int d = wd + nt * 8 + tg * 2;
        const size_t base0 = (size_t)(b * S_ + q0 + wm + g) * QKDIM_ + h * HD_ + d;
        const size_t base1 = base0 + 8 * QKDIM_;
        __half2 t;
        t.x = __float2half_rn(oc[nt][0] * inv0);
        t.y = __float2half_rn(oc[nt][1] * inv0);
        *(__half2*)(ath + base0) = t;
        t.x = __float2half_rn(oc[nt][2] * inv1);
        t.y = __float2half_rn(oc[nt][3] * inv1);
        *(__half2*)(ath + base1) = t;
    }
}

// ---------------------------------------------------------------------------
// Launch
// Inputs: 0=hidden_states 1=attention_mask(unused) 2=position_ids
//         3=Wq 4=Wk 5=Wv 6=Wo
// ---------------------------------------------------------------------------
extern "C" void kernel_launch(void* const* d_in, const int* in_sizes, int n_in,
                              void* d_out, int out_size) {
    (void)in_sizes; (void)n_in; (void)out_size;
    const float* hs  = (const float*)d_in[0];
    const int*   pos = (const int*)  d_in[2];
    const float* Wq  = (const float*)d_in[3];
    const float* Wk  = (const float*)d_in[4];
    const float* Wv  = (const float*)d_in[5];
    const float* Wo  = (const float*)d_in[6];
    float* out = (float*)d_out;

    float *qkv;
    fp16 *hsh,*qh,*kh,*kl,*vth,*vtl,*ath;
    fp16 *wallh,*walll,*woh,*wol;
    cudaGetSymbolAddress((void**)&qkv, g_qkv);
    cudaGetSymbolAddress((void**)&hsh, g_hsh);
    cudaGetSymbolAddress((void**)&qh,  g_qh);
    cudaGetSymbolAddress((void**)&kh,  g_kh);  cudaGetSymbolAddress((void**)&kl,  g_kl);
    cudaGetSymbolAddress((void**)&vth, g_vth); cudaGetSymbolAddress((void**)&vtl, g_vtl);
    cudaGetSymbolAddress((void**)&ath, g_ath);
    cudaGetSymbolAddress((void**)&wallh, g_wallh); cudaGetSymbolAddress((void**)&walll, g_walll);
    cudaGetSymbolAddress((void**)&woh, g_woh); cudaGetSymbolAddress((void**)&wol, g_wol);

    cudaFuncSetAttribute(gemm_fp16s,
        cudaFuncAttributeMaxDynamicSharedMemorySize, GEMM_SMEM);
    cudaFuncSetAttribute(gemm_fp16s_n64,
        cudaFuncAttributeMaxDynamicSharedMemorySize, N64_SMEM);
    cudaFuncSetAttribute(attn_mma_kernel,
        cudaFuncAttributeMaxDynamicSharedMemorySize, ATT_SMEM_BYTES);

    const dim3 tb(32, 8);

    // Convert hidden states to fp16 (hi only); transpose+split weights
    cvt_kernel<<<(M_ * HID_ / 4 + 255) / 256, 256>>>(hs, hsh, M_ * HID_);
    wqkv_transpose_kernel<<<dim3(NQKV_ / 32, HID_ / 32), tb>>>(
        Wq, Wk, Wv, wallh, walll);
    transpose_split_kernel<<<dim3(64, 64, 1), tb>>>(
        Wo, woh, wol, HID_, 0, QKDIM_, 0);

    // Fused QKV projection (2-MMA fp16, narrow tiles)
    gemm_fp16s_n64<<<dim3(NQKV_ / 64, M_ / 128), 256, N64_SMEM>>>(
        hsh, wallh, walll, qkv, M_, NQKV_, HID_);

    // Fused RoPE + split: qkv -> Q hi / K hi+lo
    {
        const int total = B_ * S_ * NH_ * (HD_ / 2) + B_ * S_ * (HD_ / 2);
        rope_split_kernel<<<(total + 255) / 256, 256>>>(qkv, pos, qh, kh, kl);
    }

    // Transpose+split V per batch
    transpose_split_kernel<<<dim3(8, 64, B_), tb>>>(
        qkv + QKDIM_ + HD_, vth, vtl,
        NQKV_, (size_t)S_ * NQKV_, S_, (size_t)HD_ * S_);

    // Attention (fp16 2-term flash)
    attn_mma_kernel<<<dim3(S_ / 64, NH_, B_), 256, ATT_SMEM_BYTES>>>(
        qh, kh, kl, vth, vtl, ath);

    // Output projection (2-MMA fp16, wide tiles)
    gemm_fp16s<<<dim3(HID_ / 128, M_ / 128), 256, GEMM_SMEM>>>(
        ath, woh, wol, out, M_, HID_, HID_);
}